// round 1
// baseline (speedup 1.0000x reference)
#include <cuda_runtime.h>
#include <math.h>

#define N_NODES 100000
#define N_EDGES 250000
#define DIN 32
#define DOUT 32
#define DE 13
#define ZC 448  // 14 * 32  (13 edge-attr dims + 1 bias slot) * DOUT

// -------- scratch (device globals: allocation-free at runtime) --------
__device__ float g_z[(size_t)N_NODES * ZC];     // 179.2 MB
__device__ float g_agg[(size_t)N_NODES * DOUT]; // 12.8 MB
__device__ float g_cnt[N_NODES];                // 0.4 MB

// ============================================================
// Kernel 1: z[n, d*32+o] = sum_i x[n,i] * Wbig[i, d*32+o]
//   Wbig[i, d*32+o] = nn_w[(i*32+o)*13 + d]  (d < 13)
//                   = nn_b[i*32+o]           (d == 13)
// Also zeroes g_agg / g_cnt for its nodes.
// One thread = one node; weights (57 KB) in dynamic smem, read as
// uniform-address (broadcast) LDS.128.
// ============================================================
__global__ void k1_node_z(const float* __restrict__ x,
                          const float* __restrict__ nn_w,
                          const float* __restrict__ nn_b) {
    extern __shared__ __align__(16) float Ws[];  // [32][448]
    const int tid = threadIdx.x;  // 128 threads

    for (int idx = tid; idx < 32 * ZC; idx += 128) {
        int i = idx / ZC;
        int c = idx - i * ZC;
        int d = c >> 5;
        int o = c & 31;
        Ws[idx] = (d < 13) ? nn_w[(i * 32 + o) * 13 + d] : nn_b[i * 32 + o];
    }
    __syncthreads();

    const int n = blockIdx.x * 128 + tid;
    if (n >= N_NODES) return;

    // zero aggregation buffers for this node
    {
        float4 zero4 = make_float4(0.f, 0.f, 0.f, 0.f);
        float4* ag = (float4*)(g_agg + (size_t)n * DOUT);
#pragma unroll
        for (int q = 0; q < 8; q++) ag[q] = zero4;
        g_cnt[n] = 0.f;
    }

    // load this node's x row (vectorized)
    float xr[32];
    {
        const float4* xv = (const float4*)(x + (size_t)n * DIN);
#pragma unroll
        for (int q = 0; q < 8; q++) {
            float4 v = xv[q];
            xr[q * 4 + 0] = v.x; xr[q * 4 + 1] = v.y;
            xr[q * 4 + 2] = v.z; xr[q * 4 + 3] = v.w;
        }
    }

    float* zrow = g_z + (size_t)n * ZC;

    for (int ch = 0; ch < ZC / 16; ch++) {  // 28 chunks of 16 outputs
        float acc[16];
#pragma unroll
        for (int t = 0; t < 16; t++) acc[t] = 0.f;

#pragma unroll
        for (int i = 0; i < 32; i++) {
            const float4* w4 = (const float4*)(Ws + i * ZC + ch * 16);
            const float xi = xr[i];
            float4 w;
            w = w4[0]; acc[0] += xi * w.x; acc[1] += xi * w.y; acc[2] += xi * w.z; acc[3] += xi * w.w;
            w = w4[1]; acc[4] += xi * w.x; acc[5] += xi * w.y; acc[6] += xi * w.z; acc[7] += xi * w.w;
            w = w4[2]; acc[8] += xi * w.x; acc[9] += xi * w.y; acc[10] += xi * w.z; acc[11] += xi * w.w;
            w = w4[3]; acc[12] += xi * w.x; acc[13] += xi * w.y; acc[14] += xi * w.z; acc[15] += xi * w.w;
        }

        float4* zo = (float4*)(zrow + ch * 16);
        zo[0] = make_float4(acc[0], acc[1], acc[2], acc[3]);
        zo[1] = make_float4(acc[4], acc[5], acc[6], acc[7]);
        zo[2] = make_float4(acc[8], acc[9], acc[10], acc[11]);
        zo[3] = make_float4(acc[12], acc[13], acc[14], acc[15]);
    }
}

// ============================================================
// Kernel 2: per-edge message + scatter-add (mean numerator + count)
// One warp = one edge; lane = output channel o.
// msg[o] = sum_{d<13} ea[e,d] * z[src, d*32+o] + z[src, 13*32+o]
// ============================================================
__global__ void k2_edge_scatter(const float* __restrict__ edge_attr,
                                const int* __restrict__ edge_index) {
    const int gtid = blockIdx.x * blockDim.x + threadIdx.x;
    const int e = gtid >> 5;
    const int lane = gtid & 31;
    if (e >= N_EDGES) return;

    const int src = edge_index[e];
    const int dst = edge_index[N_EDGES + e];

    float a = (lane < DE) ? edge_attr[(size_t)e * DE + lane] : 0.f;

    const float* zr = g_z + (size_t)src * ZC;
    float m = zr[13 * 32 + lane];  // bias term
#pragma unroll
    for (int d = 0; d < DE; d++) {
        float ad = __shfl_sync(0xffffffffu, a, d);
        m += ad * zr[d * 32 + lane];
    }

    atomicAdd(&g_agg[(size_t)dst * DOUT + lane], m);
    if (lane == 0) atomicAdd(&g_cnt[dst], 1.f);
}

// ============================================================
// Kernel 3: mean + root GEMV + bias -> CELU -> GRU step -> residual ReLU
// One warp = one node; lane = channel. GRU weights transposed in smem.
// ============================================================
__global__ void k3_gru(const float* __restrict__ x,
                       const float* __restrict__ root,
                       const float* __restrict__ bias,
                       const float* __restrict__ w_ih,
                       const float* __restrict__ w_hh,
                       const float* __restrict__ b_ih,
                       const float* __restrict__ b_hh,
                       float* __restrict__ out,
                       int write_h) {
    __shared__ float Rs[DIN * DOUT];     // root[i][o], o contiguous
    __shared__ float WiT[32 * 96];       // WiT[j*96+g] = w_ih[g*32+j]
    __shared__ float WhT[32 * 96];       // WhT[j*96+g] = w_hh[g*32+j]
    __shared__ float Bi[96], Bh[96], Bo[32];
    __shared__ float stage_x[8][32];
    __shared__ float stage_c[8][32];

    const int t = threadIdx.x;  // 256 threads = 8 warps
    for (int idx = t; idx < DIN * DOUT; idx += 256) Rs[idx] = root[idx];
    for (int idx = t; idx < 96 * 32; idx += 256) {
        int g = idx >> 5, j = idx & 31;
        WiT[j * 96 + g] = w_ih[idx];
        WhT[j * 96 + g] = w_hh[idx];
    }
    if (t < 96) { Bi[t] = b_ih[t]; Bh[t] = b_hh[t]; }
    if (t < 32) Bo[t] = bias[t];
    __syncthreads();

    const int w = t >> 5;
    const int lane = t & 31;
    const int n = blockIdx.x * 8 + w;  // 12500 * 8 == 100000 exactly
    if (n >= N_NODES) return;

    const float h0 = x[(size_t)n * DIN + lane];
    stage_x[w][lane] = h0;
    __syncwarp();

    const float cnt = g_cnt[n];
    float conv = g_agg[(size_t)n * DOUT + lane] / fmaxf(cnt, 1.f) + Bo[lane];
#pragma unroll
    for (int i = 0; i < 32; i++) conv += stage_x[w][i] * Rs[i * 32 + lane];

    const float c = (conv > 0.f) ? conv : expm1f(conv);
    stage_c[w][lane] = c;
    __syncwarp();

    float gr = Bi[lane], gz = Bi[32 + lane], gc = Bi[64 + lane];
    float hr = Bh[lane], hz = Bh[32 + lane], hc = Bh[64 + lane];
#pragma unroll
    for (int j = 0; j < 32; j++) {
        const float cj = stage_c[w][j];
        const float hj = stage_x[w][j];
        gr += cj * WiT[j * 96 + lane];
        gz += cj * WiT[j * 96 + 32 + lane];
        gc += cj * WiT[j * 96 + 64 + lane];
        hr += hj * WhT[j * 96 + lane];
        hz += hj * WhT[j * 96 + 32 + lane];
        hc += hj * WhT[j * 96 + 64 + lane];
    }

    const float r  = 1.f / (1.f + expf(-(gr + hr)));
    const float zg = 1.f / (1.f + expf(-(gz + hz)));
    const float nn = tanhf(gc + r * hc);
    const float h_new = (1.f - zg) * nn + zg * h0;

    out[(size_t)n * DOUT + lane] = fmaxf(h_new + h0, 0.f);
    if (write_h)
        out[(size_t)N_NODES * DOUT + (size_t)n * DOUT + lane] = h_new;
}

// ============================================================
extern "C" void kernel_launch(void* const* d_in, const int* in_sizes, int n_in,
                              void* d_out, int out_size) {
    const float* x         = (const float*)d_in[0];
    const float* edge_attr = (const float*)d_in[1];
    const float* nn_w      = (const float*)d_in[2];
    const float* nn_b      = (const float*)d_in[3];
    const float* root      = (const float*)d_in[4];
    const float* bias      = (const float*)d_in[5];
    const float* w_ih      = (const float*)d_in[6];
    const float* w_hh      = (const float*)d_in[7];
    const float* b_ih      = (const float*)d_in[8];
    const float* b_hh      = (const float*)d_in[9];
    const int* edge_index  = (const int*)d_in[10];
    float* out = (float*)d_out;

    const int smem1 = 32 * ZC * (int)sizeof(float);  // 57344 B
    cudaFuncSetAttribute(k1_node_z, cudaFuncAttributeMaxDynamicSharedMemorySize, smem1);

    const int grid1 = (N_NODES + 127) / 128;
    k1_node_z<<<grid1, 128, smem1>>>(x, nn_w, nn_b);

    const int warps2 = N_EDGES;
    const int grid2 = (warps2 * 32 + 255) / 256;
    k2_edge_scatter<<<grid2, 256>>>(edge_attr, edge_index);

    const int write_h = (out_size >= 2 * N_NODES * DOUT) ? 1 : 0;
    k3_gru<<<N_NODES / 8, 256>>>(x, root, bias, w_ih, w_hh, b_ih, b_hh, out, write_h);
}

// round 2
// speedup vs baseline: 1.0813x; 1.0813x over previous
#include <cuda_runtime.h>
#include <math.h>
#include <stdint.h>

#define N_NODES 100000
#define N_EDGES 250000
#define DIN 32
#define DOUT 32
#define DE 13
#define ZC 448          // 14*32 z-columns (13 ea dims + 1 bias slot)
#define ZPITCH 452      // padded smem row pitch (floats) to dodge STS conflicts
#define NODES_PER_BLK 64
#define KD_THREADS 256
#define SCAN_BLK 1024
#define NSCAN_BLKS ((N_NODES + SCAN_BLK - 1) / SCAN_BLK)   // 98

// -------- scratch (device globals: allocation-free) --------
__device__ float g_agg[(size_t)N_NODES * DOUT];  // 12.8 MB
__device__ float g_cnt[N_NODES];
__device__ int   g_deg[N_NODES];
__device__ int   g_offs[N_NODES];
__device__ int   g_cursor[N_NODES];
__device__ int   g_sdst[N_EDGES];
__device__ int   g_seid[N_EDGES];
__device__ int   g_bsum[NSCAN_BLKS];
__device__ int   g_bsumx[NSCAN_BLKS];

// -------- packed f32x2 helpers --------
__device__ __forceinline__ uint64_t pk2(float a, float b) {
    uint64_t r; asm("mov.b64 %0, {%1, %2};" : "=l"(r) : "f"(a), "f"(b)); return r;
}
__device__ __forceinline__ void fma2(uint64_t& d, uint64_t a, uint64_t b) {
    asm("fma.rn.f32x2 %0, %1, %2, %0;" : "+l"(d) : "l"(a), "l"(b));
}

// ============================================================
// Preprocessing kernels
// ============================================================
__global__ void kZero() {
    int i = blockIdx.x * blockDim.x + threadIdx.x;
    int stride = gridDim.x * blockDim.x;
    for (int j = i; j < N_NODES * DOUT; j += stride) g_agg[j] = 0.f;
    for (int j = i; j < N_NODES; j += stride) { g_cnt[j] = 0.f; g_deg[j] = 0; }
}

__global__ void kHist(const int* __restrict__ ei) {
    int e = blockIdx.x * blockDim.x + threadIdx.x;
    if (e >= N_EDGES) return;
    atomicAdd(&g_deg[ei[e]], 1);
    atomicAdd(&g_cnt[ei[N_EDGES + e]], 1.f);
}

__global__ void kScan1() {  // per-block sums of g_deg
    __shared__ int sh[32];
    int i = blockIdx.x * SCAN_BLK + threadIdx.x;
    int v = (i < N_NODES) ? g_deg[i] : 0;
#pragma unroll
    for (int o = 16; o; o >>= 1) v += __shfl_down_sync(0xffffffffu, v, o);
    if ((threadIdx.x & 31) == 0) sh[threadIdx.x >> 5] = v;
    __syncthreads();
    if (threadIdx.x < 32) {
        int w = sh[threadIdx.x];
#pragma unroll
        for (int o = 16; o; o >>= 1) w += __shfl_down_sync(0xffffffffu, w, o);
        if (threadIdx.x == 0) g_bsum[blockIdx.x] = w;
    }
}

__global__ void kScan2() {  // exclusive scan of 98 block sums (1 block, 128 thr)
    __shared__ int sh[4];
    int t = threadIdx.x, lane = t & 31, w = t >> 5;
    int v = (t < NSCAN_BLKS) ? g_bsum[t] : 0;
    int s = v;
#pragma unroll
    for (int o = 1; o < 32; o <<= 1) {
        int u = __shfl_up_sync(0xffffffffu, s, o);
        if (lane >= o) s += u;
    }
    if (lane == 31) sh[w] = s;
    __syncthreads();
    int base = 0;
    for (int k = 0; k < w; k++) base += sh[k];
    if (t < NSCAN_BLKS) g_bsumx[t] = base + s - v;
}

__global__ void kScan3() {  // full exclusive scan -> g_offs, g_cursor
    __shared__ int wsum[32];
    int t = threadIdx.x, lane = t & 31, w = t >> 5;
    int i = blockIdx.x * SCAN_BLK + t;
    int v = (i < N_NODES) ? g_deg[i] : 0;
    int s = v;
#pragma unroll
    for (int o = 1; o < 32; o <<= 1) {
        int u = __shfl_up_sync(0xffffffffu, s, o);
        if (lane >= o) s += u;
    }
    if (lane == 31) wsum[w] = s;
    __syncthreads();
    if (w == 0) {
        int ws = wsum[lane];
#pragma unroll
        for (int o = 1; o < 32; o <<= 1) {
            int u = __shfl_up_sync(0xffffffffu, ws, o);
            if (lane >= o) ws += u;
        }
        wsum[lane] = ws;
    }
    __syncthreads();
    int base = (w > 0) ? wsum[w - 1] : 0;
    int excl = g_bsumx[blockIdx.x] + base + s - v;
    if (i < N_NODES) { g_offs[i] = excl; g_cursor[i] = excl; }
}

__global__ void kScat(const int* __restrict__ ei) {
    int e = blockIdx.x * blockDim.x + threadIdx.x;
    if (e >= N_EDGES) return;
    int src = ei[e];
    int pos = atomicAdd(&g_cursor[src], 1);
    g_sdst[pos] = ei[N_EDGES + e];
    g_seid[pos] = e;
}

// ============================================================
// Fused kernel: per-64-node tile, compute z in SMEM (f32x2 GEMM),
// then apply this tile's out-edges: msg = ea'.z, atomic scatter to agg.
// ============================================================
__global__ void __launch_bounds__(KD_THREADS, 1)
kFused(const float* __restrict__ x,
       const float* __restrict__ nn_w,
       const float* __restrict__ nn_b,
       const float* __restrict__ edge_attr) {
    extern __shared__ __align__(16) float sm[];
    float* Ws = sm;               // [32][448] = 57344 B
    float* zs = sm + 32 * ZC;     // [64][452] = 115712 B

    const int t = threadIdx.x;    // 256 = 8 warps
    const int lane = t & 31;
    const int w = t >> 5;

    // stage weights: Ws[i*448 + d*32 + o]
    for (int idx = t; idx < 32 * ZC; idx += KD_THREADS) {
        int i = idx / ZC;
        int c = idx - i * ZC;
        int d = c >> 5, o = c & 31;
        Ws[idx] = (d < 13) ? nn_w[(i * 32 + o) * 13 + d] : nn_b[i * 32 + o];
    }
    __syncthreads();

    // ---- phase 1: z tile GEMM (lane = node) ----
    const int g = w >> 2;                 // node half (0/1)
    const int cw = w & 3;                 // column quarter
    const int ln = g * 32 + lane;         // local node 0..63
    const int n = blockIdx.x * NODES_PER_BLK + ln;

    uint64_t xp[32];                      // x row packed (xi, xi)
    if (n < N_NODES) {
        const float4* xv = (const float4*)(x + (size_t)n * DIN);
#pragma unroll
        for (int q = 0; q < 8; q++) {
            float4 v = xv[q];
            xp[q * 4 + 0] = pk2(v.x, v.x);
            xp[q * 4 + 1] = pk2(v.y, v.y);
            xp[q * 4 + 2] = pk2(v.z, v.z);
            xp[q * 4 + 3] = pk2(v.w, v.w);
        }
    } else {
#pragma unroll
        for (int q = 0; q < 32; q++) xp[q] = 0ull;
    }

#pragma unroll 1
    for (int c = 0; c < 7; c++) {         // 7 chunks of 16 cols
        const int c0 = cw * 112 + c * 16;
        uint64_t acc[8];
#pragma unroll
        for (int q = 0; q < 8; q++) acc[q] = 0ull;

#pragma unroll
        for (int i = 0; i < 32; i++) {
            const ulonglong2* wp = (const ulonglong2*)(Ws + i * ZC + c0);
            ulonglong2 wa = wp[0], wb = wp[1];
            fma2(acc[0], xp[i], wa.x); fma2(acc[1], xp[i], wa.y);
            fma2(acc[2], xp[i], wb.x); fma2(acc[3], xp[i], wb.y);
            wa = wp[2]; wb = wp[3];
            fma2(acc[4], xp[i], wa.x); fma2(acc[5], xp[i], wa.y);
            fma2(acc[6], xp[i], wb.x); fma2(acc[7], xp[i], wb.y);
        }

        ulonglong2* zo = (ulonglong2*)(zs + (size_t)ln * ZPITCH + c0);
        ulonglong2 s0, s1, s2, s3;
        s0.x = acc[0]; s0.y = acc[1]; s1.x = acc[2]; s1.y = acc[3];
        s2.x = acc[4]; s2.y = acc[5]; s3.x = acc[6]; s3.y = acc[7];
        zo[0] = s0; zo[1] = s1; zo[2] = s2; zo[3] = s3;
    }
    __syncthreads();

    // ---- phase 2: edges of this tile (warp w -> local nodes [w*8, w*8+8)) ----
    for (int q = 0; q < 8; q++) {
        const int ln2 = w * 8 + q;
        const int n2 = blockIdx.x * NODES_PER_BLK + ln2;
        if (n2 >= N_NODES) break;
        const int m = g_deg[n2];
        if (m == 0) continue;
        const int off = g_offs[n2];

        float zv[14];
#pragma unroll
        for (int d = 0; d < 14; d++) zv[d] = zs[(size_t)ln2 * ZPITCH + d * 32 + lane];

        int eid = g_seid[off];
        int dst = g_sdst[off];
        float a = (lane < DE) ? edge_attr[(size_t)eid * DE + lane] : 0.f;

        for (int j = 0; j < m; j++) {
            int eid2 = 0, dst2 = 0; float a2 = 0.f;
            if (j + 1 < m) {
                eid2 = g_seid[off + j + 1];
                dst2 = g_sdst[off + j + 1];
                a2 = (lane < DE) ? edge_attr[(size_t)eid2 * DE + lane] : 0.f;
            }
            float msg = zv[13];
#pragma unroll
            for (int d = 0; d < DE; d++)
                msg += __shfl_sync(0xffffffffu, a, d) * zv[d];
            atomicAdd(&g_agg[(size_t)dst * DOUT + lane], msg);
            eid = eid2; dst = dst2; a = a2;
        }
    }
}

// ============================================================
// Kernel 3: mean + root GEMV + bias -> CELU -> GRU -> residual ReLU
// ============================================================
__global__ void k3_gru(const float* __restrict__ x,
                       const float* __restrict__ root,
                       const float* __restrict__ bias,
                       const float* __restrict__ w_ih,
                       const float* __restrict__ w_hh,
                       const float* __restrict__ b_ih,
                       const float* __restrict__ b_hh,
                       float* __restrict__ out,
                       int write_h) {
    __shared__ float Rs[DIN * DOUT];
    __shared__ float WiT[32 * 96];
    __shared__ float WhT[32 * 96];
    __shared__ float Bi[96], Bh[96], Bo[32];
    __shared__ float stage_x[8][32];
    __shared__ float stage_c[8][32];

    const int t = threadIdx.x;  // 256 threads
    for (int idx = t; idx < DIN * DOUT; idx += 256) Rs[idx] = root[idx];
    for (int idx = t; idx < 96 * 32; idx += 256) {
        int g = idx >> 5, j = idx & 31;
        WiT[j * 96 + g] = w_ih[idx];
        WhT[j * 96 + g] = w_hh[idx];
    }
    if (t < 96) { Bi[t] = b_ih[t]; Bh[t] = b_hh[t]; }
    if (t < 32) Bo[t] = bias[t];
    __syncthreads();

    const int w = t >> 5;
    const int lane = t & 31;
    const int n = blockIdx.x * 8 + w;
    if (n >= N_NODES) return;

    const float h0 = x[(size_t)n * DIN + lane];
    stage_x[w][lane] = h0;
    __syncwarp();

    const float cnt = g_cnt[n];
    float conv = g_agg[(size_t)n * DOUT + lane] / fmaxf(cnt, 1.f) + Bo[lane];
#pragma unroll
    for (int i = 0; i < 32; i++) conv += stage_x[w][i] * Rs[i * 32 + lane];

    const float c = (conv > 0.f) ? conv : expm1f(conv);
    stage_c[w][lane] = c;
    __syncwarp();

    float gr = Bi[lane], gz = Bi[32 + lane], gc = Bi[64 + lane];
    float hr = Bh[lane], hz = Bh[32 + lane], hc = Bh[64 + lane];
#pragma unroll
    for (int j = 0; j < 32; j++) {
        const float cj = stage_c[w][j];
        const float hj = stage_x[w][j];
        gr += cj * WiT[j * 96 + lane];
        gz += cj * WiT[j * 96 + 32 + lane];
        gc += cj * WiT[j * 96 + 64 + lane];
        hr += hj * WhT[j * 96 + lane];
        hz += hj * WhT[j * 96 + 32 + lane];
        hc += hj * WhT[j * 96 + 64 + lane];
    }

    const float r  = 1.f / (1.f + expf(-(gr + hr)));
    const float zg = 1.f / (1.f + expf(-(gz + hz)));
    const float nn = tanhf(gc + r * hc);
    const float h_new = (1.f - zg) * nn + zg * h0;

    out[(size_t)n * DOUT + lane] = fmaxf(h_new + h0, 0.f);
    if (write_h)
        out[(size_t)N_NODES * DOUT + (size_t)n * DOUT + lane] = h_new;
}

// ============================================================
extern "C" void kernel_launch(void* const* d_in, const int* in_sizes, int n_in,
                              void* d_out, int out_size) {
    const float* x         = (const float*)d_in[0];
    const float* edge_attr = (const float*)d_in[1];
    const float* nn_w      = (const float*)d_in[2];
    const float* nn_b      = (const float*)d_in[3];
    const float* root      = (const float*)d_in[4];
    const float* bias      = (const float*)d_in[5];
    const float* w_ih      = (const float*)d_in[6];
    const float* w_hh      = (const float*)d_in[7];
    const float* b_ih      = (const float*)d_in[8];
    const float* b_hh      = (const float*)d_in[9];
    const int* edge_index  = (const int*)d_in[10];
    float* out = (float*)d_out;

    const int smemF = (32 * ZC + NODES_PER_BLK * ZPITCH) * (int)sizeof(float); // 173056
    cudaFuncSetAttribute(kFused, cudaFuncAttributeMaxDynamicSharedMemorySize, smemF);

    const int gridE = (N_EDGES + 255) / 256;

    kZero<<<512, 256>>>();
    kHist<<<gridE, 256>>>(edge_index);
    kScan1<<<NSCAN_BLKS, SCAN_BLK>>>();
    kScan2<<<1, 128>>>();
    kScan3<<<NSCAN_BLKS, SCAN_BLK>>>();
    kScat<<<gridE, 256>>>(edge_index);

    const int gridF = (N_NODES + NODES_PER_BLK - 1) / NODES_PER_BLK;  // 1563
    kFused<<<gridF, KD_THREADS, smemF>>>(x, nn_w, nn_b, edge_attr);

    const int write_h = (out_size >= 2 * N_NODES * DOUT) ? 1 : 0;
    k3_gru<<<N_NODES / 8, 256>>>(x, root, bias, w_ih, w_hh, b_ih, b_hh, out, write_h);
}

// round 3
// speedup vs baseline: 1.1336x; 1.0484x over previous
#include <cuda_runtime.h>
#include <math.h>
#include <stdint.h>

#define N_NODES 100000
#define N_EDGES 250000
#define DIN 32
#define DOUT 32
#define DE 13
#define ZC 448          // 14*32 z-columns (13 ea dims + 1 bias slot)
#define ZPITCH 452      // padded smem row pitch (floats): bank stride 4
#define NODES_PER_BLK 64
#define KF_THREADS 512
#define SCAN_BLK 1024
#define NSCAN_BLKS ((N_NODES + SCAN_BLK - 1) / SCAN_BLK)   // 98

// -------- scratch (device globals: allocation-free) --------
__device__ float g_agg[(size_t)N_NODES * DOUT];  // 12.8 MB
__device__ float g_cnt[N_NODES];
__device__ int   g_deg[N_NODES];
__device__ int   g_offs[N_NODES];
__device__ int   g_cursor[N_NODES];
__device__ int   g_sdst[N_EDGES];
__device__ int   g_ssrc[N_EDGES];
__device__ int   g_seid[N_EDGES];
__device__ int   g_bsum[NSCAN_BLKS];
__device__ int   g_bsumx[NSCAN_BLKS];

// ============================================================
// Preprocessing
// ============================================================
__global__ void kZero() {
    int i = blockIdx.x * blockDim.x + threadIdx.x;
    int stride = gridDim.x * blockDim.x;
    for (int j = i; j < N_NODES * DOUT; j += stride) g_agg[j] = 0.f;
    for (int j = i; j < N_NODES; j += stride) { g_cnt[j] = 0.f; g_deg[j] = 0; }
}

__global__ void kHist(const int* __restrict__ ei) {
    int e = blockIdx.x * blockDim.x + threadIdx.x;
    if (e >= N_EDGES) return;
    atomicAdd(&g_deg[ei[e]], 1);
    atomicAdd(&g_cnt[ei[N_EDGES + e]], 1.f);
}

__global__ void kScan1() {  // per-block sums of g_deg
    __shared__ int sh[32];
    int i = blockIdx.x * SCAN_BLK + threadIdx.x;
    int v = (i < N_NODES) ? g_deg[i] : 0;
#pragma unroll
    for (int o = 16; o; o >>= 1) v += __shfl_down_sync(0xffffffffu, v, o);
    if ((threadIdx.x & 31) == 0) sh[threadIdx.x >> 5] = v;
    __syncthreads();
    if (threadIdx.x < 32) {
        int w = sh[threadIdx.x];
#pragma unroll
        for (int o = 16; o; o >>= 1) w += __shfl_down_sync(0xffffffffu, w, o);
        if (threadIdx.x == 0) g_bsum[blockIdx.x] = w;
    }
}

__global__ void kScan2() {  // exclusive scan of 98 block sums
    __shared__ int sh[4];
    int t = threadIdx.x, lane = t & 31, w = t >> 5;
    int v = (t < NSCAN_BLKS) ? g_bsum[t] : 0;
    int s = v;
#pragma unroll
    for (int o = 1; o < 32; o <<= 1) {
        int u = __shfl_up_sync(0xffffffffu, s, o);
        if (lane >= o) s += u;
    }
    if (lane == 31) sh[w] = s;
    __syncthreads();
    int base = 0;
    for (int k = 0; k < w; k++) base += sh[k];
    if (t < NSCAN_BLKS) g_bsumx[t] = base + s - v;
}

__global__ void kScan3() {  // full exclusive scan -> g_offs, g_cursor
    __shared__ int wsum[32];
    int t = threadIdx.x, lane = t & 31, w = t >> 5;
    int i = blockIdx.x * SCAN_BLK + t;
    int v = (i < N_NODES) ? g_deg[i] : 0;
    int s = v;
#pragma unroll
    for (int o = 1; o < 32; o <<= 1) {
        int u = __shfl_up_sync(0xffffffffu, s, o);
        if (lane >= o) s += u;
    }
    if (lane == 31) wsum[w] = s;
    __syncthreads();
    if (w == 0) {
        int ws = wsum[lane];
#pragma unroll
        for (int o = 1; o < 32; o <<= 1) {
            int u = __shfl_up_sync(0xffffffffu, ws, o);
            if (lane >= o) ws += u;
        }
        wsum[lane] = ws;
    }
    __syncthreads();
    int base = (w > 0) ? wsum[w - 1] : 0;
    int excl = g_bsumx[blockIdx.x] + base + s - v;
    if (i < N_NODES) { g_offs[i] = excl; g_cursor[i] = excl; }
}

__global__ void kScat(const int* __restrict__ ei) {
    int e = blockIdx.x * blockDim.x + threadIdx.x;
    if (e >= N_EDGES) return;
    int src = ei[e];
    int pos = atomicAdd(&g_cursor[src], 1);
    g_sdst[pos] = ei[N_EDGES + e];
    g_ssrc[pos] = src;
    g_seid[pos] = e;
}

// ============================================================
// Fused kernel: 64-node tile.
// Phase 1: z tile in SMEM (scalar FFMA GEMM, lane=node, warp=col octant).
// Phase 2: tile's contiguous sorted-edge segment, warp-strided:
//          msg = ea . z[src], RED-scatter into g_agg[dst].
// ============================================================
__global__ void __launch_bounds__(KF_THREADS, 1)
kFused(const float* __restrict__ x,
       const float* __restrict__ nn_w,
       const float* __restrict__ nn_b,
       const float* __restrict__ edge_attr) {
    extern __shared__ __align__(16) float sm[];
    float* Ws = sm;               // [32][448] = 57344 B
    float* zs = sm + 32 * ZC;     // [64][452] = 115712 B

    const int t = threadIdx.x;    // 512 = 16 warps
    const int lane = t & 31;
    const int w = t >> 5;

    // stage weights: Ws[i*448 + d*32 + o]
    for (int idx = t; idx < 32 * ZC; idx += KF_THREADS) {
        int i = idx / ZC;
        int c = idx - i * ZC;
        int d = c >> 5, o = c & 31;
        Ws[idx] = (d < 13) ? nn_w[(i * 32 + o) * 13 + d] : nn_b[i * 32 + o];
    }
    __syncthreads();

    // ---- phase 1: lane = node (2 halves of 32), warp covers 56 cols ----
    const int g  = w >> 3;                 // node half (0/1)
    const int cw = w & 7;                  // column octant (56 cols)
    const int ln = g * 32 + lane;          // local node 0..63
    const int n  = blockIdx.x * NODES_PER_BLK + ln;

    float xr[32];
    if (n < N_NODES) {
        const float4* xv = (const float4*)(x + (size_t)n * DIN);
#pragma unroll
        for (int q = 0; q < 8; q++) {
            float4 v = xv[q];
            xr[q * 4 + 0] = v.x; xr[q * 4 + 1] = v.y;
            xr[q * 4 + 2] = v.z; xr[q * 4 + 3] = v.w;
        }
    } else {
#pragma unroll
        for (int q = 0; q < 32; q++) xr[q] = 0.f;
    }

    float* zrow = zs + (size_t)ln * ZPITCH + cw * 56;

#pragma unroll 1
    for (int c = 0; c < 7; c++) {          // 7 chunks of 8 cols
        const int c0 = cw * 56 + c * 8;
        float acc[8];
#pragma unroll
        for (int q = 0; q < 8; q++) acc[q] = 0.f;

#pragma unroll
        for (int i = 0; i < 32; i++) {
            const float4* w4 = (const float4*)(Ws + i * ZC + c0);
            const float xi = xr[i];
            float4 wa = w4[0], wb = w4[1];
            acc[0] += xi * wa.x; acc[1] += xi * wa.y;
            acc[2] += xi * wa.z; acc[3] += xi * wa.w;
            acc[4] += xi * wb.x; acc[5] += xi * wb.y;
            acc[6] += xi * wb.z; acc[7] += xi * wb.w;
        }

        float4* zo = (float4*)(zrow + c * 8);
        zo[0] = make_float4(acc[0], acc[1], acc[2], acc[3]);
        zo[1] = make_float4(acc[4], acc[5], acc[6], acc[7]);
    }
    __syncthreads();

    // ---- phase 2: contiguous edge segment of this tile, warp-strided ----
    const int base = blockIdx.x * NODES_PER_BLK;
    const int tileEnd = base + NODES_PER_BLK;
    const int o0 = g_offs[base];
    const int o1 = (tileEnd >= N_NODES) ? N_EDGES : g_offs[tileEnd];

    for (int j = o0 + w; j < o1; j += 16) {
        const int src = g_ssrc[j];
        const int dst = g_sdst[j];
        const int eid = g_seid[j];
        const int ls = src - base;

        float a = (lane < DE) ? edge_attr[(size_t)eid * DE + lane] : 0.f;

        const float* zr = zs + (size_t)ls * ZPITCH;
        float msg = zr[13 * 32 + lane];
#pragma unroll
        for (int d = 0; d < DE; d++)
            msg += __shfl_sync(0xffffffffu, a, d) * zr[d * 32 + lane];

        atomicAdd(&g_agg[(size_t)dst * DOUT + lane], msg);
    }
}

// ============================================================
// Kernel 3: mean + root GEMV + bias -> CELU -> GRU -> residual ReLU
// ============================================================
__global__ void k3_gru(const float* __restrict__ x,
                       const float* __restrict__ root,
                       const float* __restrict__ bias,
                       const float* __restrict__ w_ih,
                       const float* __restrict__ w_hh,
                       const float* __restrict__ b_ih,
                       const float* __restrict__ b_hh,
                       float* __restrict__ out,
                       int write_h) {
    __shared__ float Rs[DIN * DOUT];
    __shared__ float WiT[32 * 96];
    __shared__ float WhT[32 * 96];
    __shared__ float Bi[96], Bh[96], Bo[32];
    __shared__ float stage_x[8][32];
    __shared__ float stage_c[8][32];

    const int t = threadIdx.x;  // 256 threads
    for (int idx = t; idx < DIN * DOUT; idx += 256) Rs[idx] = root[idx];
    for (int idx = t; idx < 96 * 32; idx += 256) {
        int g = idx >> 5, j = idx & 31;
        WiT[j * 96 + g] = w_ih[idx];
        WhT[j * 96 + g] = w_hh[idx];
    }
    if (t < 96) { Bi[t] = b_ih[t]; Bh[t] = b_hh[t]; }
    if (t < 32) Bo[t] = bias[t];
    __syncthreads();

    const int w = t >> 5;
    const int lane = t & 31;
    const int n = blockIdx.x * 8 + w;
    if (n >= N_NODES) return;

    const float h0 = x[(size_t)n * DIN + lane];
    stage_x[w][lane] = h0;
    __syncwarp();

    const float cnt = g_cnt[n];
    float conv = g_agg[(size_t)n * DOUT + lane] / fmaxf(cnt, 1.f) + Bo[lane];
#pragma unroll
    for (int i = 0; i < 32; i++) conv += stage_x[w][i] * Rs[i * 32 + lane];

    const float c = (conv > 0.f) ? conv : expm1f(conv);
    stage_c[w][lane] = c;
    __syncwarp();

    float gr = Bi[lane], gz = Bi[32 + lane], gc = Bi[64 + lane];
    float hr = Bh[lane], hz = Bh[32 + lane], hc = Bh[64 + lane];
#pragma unroll
    for (int j = 0; j < 32; j++) {
        const float cj = stage_c[w][j];
        const float hj = stage_x[w][j];
        gr += cj * WiT[j * 96 + lane];
        gz += cj * WiT[j * 96 + 32 + lane];
        gc += cj * WiT[j * 96 + 64 + lane];
        hr += hj * WhT[j * 96 + lane];
        hz += hj * WhT[j * 96 + 32 + lane];
        hc += hj * WhT[j * 96 + 64 + lane];
    }

    const float r  = 1.f / (1.f + expf(-(gr + hr)));
    const float zg = 1.f / (1.f + expf(-(gz + hz)));
    const float nn = tanhf(gc + r * hc);
    const float h_new = (1.f - zg) * nn + zg * h0;

    out[(size_t)n * DOUT + lane] = fmaxf(h_new + h0, 0.f);
    if (write_h)
        out[(size_t)N_NODES * DOUT + (size_t)n * DOUT + lane] = h_new;
}

// ============================================================
extern "C" void kernel_launch(void* const* d_in, const int* in_sizes, int n_in,
                              void* d_out, int out_size) {
    const float* x         = (const float*)d_in[0];
    const float* edge_attr = (const float*)d_in[1];
    const float* nn_w      = (const float*)d_in[2];
    const float* nn_b      = (const float*)d_in[3];
    const float* root      = (const float*)d_in[4];
    const float* bias      = (const float*)d_in[5];
    const float* w_ih      = (const float*)d_in[6];
    const float* w_hh      = (const float*)d_in[7];
    const float* b_ih      = (const float*)d_in[8];
    const float* b_hh      = (const float*)d_in[9];
    const int* edge_index  = (const int*)d_in[10];
    float* out = (float*)d_out;

    const int smemF = (32 * ZC + NODES_PER_BLK * ZPITCH) * (int)sizeof(float); // 173056
    cudaFuncSetAttribute(kFused, cudaFuncAttributeMaxDynamicSharedMemorySize, smemF);

    const int gridE = (N_EDGES + 255) / 256;

    kZero<<<512, 256>>>();
    kHist<<<gridE, 256>>>(edge_index);
    kScan1<<<NSCAN_BLKS, SCAN_BLK>>>();
    kScan2<<<1, 128>>>();
    kScan3<<<NSCAN_BLKS, SCAN_BLK>>>();
    kScat<<<gridE, 256>>>(edge_index);

    const int gridF = (N_NODES + NODES_PER_BLK - 1) / NODES_PER_BLK;  // 1563
    kFused<<<gridF, KF_THREADS, smemF>>>(x, nn_w, nn_b, edge_attr);

    const int write_h = (out_size >= 2 * N_NODES * DOUT) ? 1 : 0;
    k3_gru<<<N_NODES / 8, 256>>>(x, root, bias, w_ih, w_hh, b_ih, b_hh, out, write_h);
}

// round 4
// speedup vs baseline: 2.0100x; 1.7731x over previous
#include <cuda_runtime.h>
#include <math.h>
#include <stdint.h>

#define N_NODES 100000
#define N_EDGES 250000
#define DIN 32
#define DOUT 32
#define DE 13
#define ZC 448          // 14*32 z-columns (13 ea dims + 1 bias slot)
#define ZPITCH 452      // smem z row pitch (floats)
#define NODES_PER_BLK 64
#define KF_THREADS 512
#define SCAN_BLK 1024
#define NSCAN_BLKS ((N_NODES + SCAN_BLK - 1) / SCAN_BLK)   // 98
#define GRID3 888       // 6 blocks/SM * 148
#define WP 97           // padded transposed-weight pitch (97 mod 32 = 1)

// -------- scratch (device globals: allocation-free) --------
__device__ float g_agg[(size_t)N_NODES * DOUT];  // 12.8 MB
__device__ float g_cnt[N_NODES];
__device__ int   g_deg[N_NODES];
__device__ int   g_offs[N_NODES];
__device__ int   g_cursor[N_NODES];
__device__ int   g_sdst[N_EDGES];
__device__ int   g_ssrc[N_EDGES];
__device__ int   g_seid[N_EDGES];
__device__ int   g_bsum[NSCAN_BLKS];
__device__ int   g_bsumx[NSCAN_BLKS];

// ============================================================
// Preprocessing
// ============================================================
__global__ void kZero() {
    int i = blockIdx.x * blockDim.x + threadIdx.x;
    int stride = gridDim.x * blockDim.x;
    for (int j = i; j < N_NODES * DOUT; j += stride) g_agg[j] = 0.f;
    for (int j = i; j < N_NODES; j += stride) { g_cnt[j] = 0.f; g_deg[j] = 0; }
}

__global__ void kHist(const int* __restrict__ ei) {
    int e = blockIdx.x * blockDim.x + threadIdx.x;
    if (e >= N_EDGES) return;
    atomicAdd(&g_deg[ei[e]], 1);
    atomicAdd(&g_cnt[ei[N_EDGES + e]], 1.f);
}

__global__ void kScan1() {  // per-block sums of g_deg
    __shared__ int sh[32];
    int i = blockIdx.x * SCAN_BLK + threadIdx.x;
    int v = (i < N_NODES) ? g_deg[i] : 0;
#pragma unroll
    for (int o = 16; o; o >>= 1) v += __shfl_down_sync(0xffffffffu, v, o);
    if ((threadIdx.x & 31) == 0) sh[threadIdx.x >> 5] = v;
    __syncthreads();
    if (threadIdx.x < 32) {
        int w = sh[threadIdx.x];
#pragma unroll
        for (int o = 16; o; o >>= 1) w += __shfl_down_sync(0xffffffffu, w, o);
        if (threadIdx.x == 0) g_bsum[blockIdx.x] = w;
    }
}

__global__ void kScan2() {  // exclusive scan of 98 block sums
    __shared__ int sh[4];
    int t = threadIdx.x, lane = t & 31, w = t >> 5;
    int v = (t < NSCAN_BLKS) ? g_bsum[t] : 0;
    int s = v;
#pragma unroll
    for (int o = 1; o < 32; o <<= 1) {
        int u = __shfl_up_sync(0xffffffffu, s, o);
        if (lane >= o) s += u;
    }
    if (lane == 31) sh[w] = s;
    __syncthreads();
    int base = 0;
    for (int k = 0; k < w; k++) base += sh[k];
    if (t < NSCAN_BLKS) g_bsumx[t] = base + s - v;
}

__global__ void kScan3() {  // full exclusive scan -> g_offs, g_cursor
    __shared__ int wsum[32];
    int t = threadIdx.x, lane = t & 31, w = t >> 5;
    int i = blockIdx.x * SCAN_BLK + t;
    int v = (i < N_NODES) ? g_deg[i] : 0;
    int s = v;
#pragma unroll
    for (int o = 1; o < 32; o <<= 1) {
        int u = __shfl_up_sync(0xffffffffu, s, o);
        if (lane >= o) s += u;
    }
    if (lane == 31) wsum[w] = s;
    __syncthreads();
    if (w == 0) {
        int ws = wsum[lane];
#pragma unroll
        for (int o = 1; o < 32; o <<= 1) {
            int u = __shfl_up_sync(0xffffffffu, ws, o);
            if (lane >= o) ws += u;
        }
        wsum[lane] = ws;
    }
    __syncthreads();
    int base = (w > 0) ? wsum[w - 1] : 0;
    int excl = g_bsumx[blockIdx.x] + base + s - v;
    if (i < N_NODES) { g_offs[i] = excl; g_cursor[i] = excl; }
}

__global__ void kScat(const int* __restrict__ ei) {
    int e = blockIdx.x * blockDim.x + threadIdx.x;
    if (e >= N_EDGES) return;
    int src = ei[e];
    int pos = atomicAdd(&g_cursor[src], 1);
    g_sdst[pos] = ei[N_EDGES + e];
    g_ssrc[pos] = src;
    g_seid[pos] = e;
}

// ============================================================
// Fused NNConv kernel: 64-node tile.
// Phase 1: z tile in SMEM (scalar FFMA GEMM, lane=node, warp=col octant).
// Phase 2: tile's contiguous sorted-edge segment, warp-strided scatter.
// ============================================================
__global__ void __launch_bounds__(KF_THREADS, 1)
kFused(const float* __restrict__ x,
       const float* __restrict__ nn_w,
       const float* __restrict__ nn_b,
       const float* __restrict__ edge_attr) {
    extern __shared__ __align__(16) float sm[];
    float* Ws = sm;               // [32][448] = 57344 B
    float* zs = sm + 32 * ZC;     // [64][452] = 115712 B

    const int t = threadIdx.x;    // 512 = 16 warps
    const int lane = t & 31;
    const int w = t >> 5;

    for (int idx = t; idx < 32 * ZC; idx += KF_THREADS) {
        int i = idx / ZC;
        int c = idx - i * ZC;
        int d = c >> 5, o = c & 31;
        Ws[idx] = (d < 13) ? nn_w[(i * 32 + o) * 13 + d] : nn_b[i * 32 + o];
    }
    __syncthreads();

    // ---- phase 1: lane = node (2 halves of 32), warp covers 56 cols ----
    const int g  = w >> 3;
    const int cw = w & 7;
    const int ln = g * 32 + lane;
    const int n  = blockIdx.x * NODES_PER_BLK + ln;

    float xr[32];
    if (n < N_NODES) {
        const float4* xv = (const float4*)(x + (size_t)n * DIN);
#pragma unroll
        for (int q = 0; q < 8; q++) {
            float4 v = xv[q];
            xr[q * 4 + 0] = v.x; xr[q * 4 + 1] = v.y;
            xr[q * 4 + 2] = v.z; xr[q * 4 + 3] = v.w;
        }
    } else {
#pragma unroll
        for (int q = 0; q < 32; q++) xr[q] = 0.f;
    }

    float* zrow = zs + (size_t)ln * ZPITCH + cw * 56;

#pragma unroll 1
    for (int c = 0; c < 7; c++) {
        const int c0 = cw * 56 + c * 8;
        float acc[8];
#pragma unroll
        for (int q = 0; q < 8; q++) acc[q] = 0.f;

#pragma unroll
        for (int i = 0; i < 32; i++) {
            const float4* w4 = (const float4*)(Ws + i * ZC + c0);
            const float xi = xr[i];
            float4 wa = w4[0], wb = w4[1];
            acc[0] += xi * wa.x; acc[1] += xi * wa.y;
            acc[2] += xi * wa.z; acc[3] += xi * wa.w;
            acc[4] += xi * wb.x; acc[5] += xi * wb.y;
            acc[6] += xi * wb.z; acc[7] += xi * wb.w;
        }

        float4* zo = (float4*)(zrow + c * 8);
        zo[0] = make_float4(acc[0], acc[1], acc[2], acc[3]);
        zo[1] = make_float4(acc[4], acc[5], acc[6], acc[7]);
    }
    __syncthreads();

    // ---- phase 2: contiguous edge segment of this tile, warp-strided ----
    const int base = blockIdx.x * NODES_PER_BLK;
    const int tileEnd = base + NODES_PER_BLK;
    const int o0 = g_offs[base];
    const int o1 = (tileEnd >= N_NODES) ? N_EDGES : g_offs[tileEnd];

    for (int j = o0 + w; j < o1; j += 16) {
        const int src = g_ssrc[j];
        const int dst = g_sdst[j];
        const int eid = g_seid[j];
        const int ls = src - base;

        float a = (lane < DE) ? edge_attr[(size_t)eid * DE + lane] : 0.f;

        const float* zr = zs + (size_t)ls * ZPITCH;
        float msg = zr[13 * 32 + lane];
#pragma unroll
        for (int d = 0; d < DE; d++)
            msg += __shfl_sync(0xffffffffu, a, d) * zr[d * 32 + lane];

        atomicAdd(&g_agg[(size_t)dst * DOUT + lane], msg);
    }
}

// ============================================================
// Kernel 3: mean + root GEMV + bias -> CELU -> GRU -> residual ReLU
// Grid-stride, conflict-free padded transposed weights (pitch 97).
// ============================================================
__global__ void __launch_bounds__(256)
k3_gru(const float* __restrict__ x,
       const float* __restrict__ root,
       const float* __restrict__ bias,
       const float* __restrict__ w_ih,
       const float* __restrict__ w_hh,
       const float* __restrict__ b_ih,
       const float* __restrict__ b_hh,
       float* __restrict__ out,
       int write_h) {
    __shared__ float Rs[DIN * DOUT];
    __shared__ float WiT[32 * WP];       // WiT[j*WP+g] = w_ih[g*32+j]
    __shared__ float WhT[32 * WP];
    __shared__ float Bi[96], Bh[96], Bo[32];
    __shared__ float stage_x[8][32];
    __shared__ float stage_c[8][32];

    const int t = threadIdx.x;  // 256 threads
    for (int idx = t; idx < DIN * DOUT; idx += 256) Rs[idx] = root[idx];
    for (int idx = t; idx < 96 * 32; idx += 256) {
        int g = idx >> 5, j = idx & 31;      // consecutive idx -> consecutive j
        WiT[j * WP + g] = w_ih[idx];         // lane stride WP=97 -> conflict-free
        WhT[j * WP + g] = w_hh[idx];
    }
    if (t < 96) { Bi[t] = b_ih[t]; Bh[t] = b_hh[t]; }
    if (t < 32) Bo[t] = bias[t];
    __syncthreads();

    const int w = t >> 5;
    const int lane = t & 31;

    for (int n = blockIdx.x * 8 + w; n < N_NODES; n += GRID3 * 8) {
        const float h0 = x[(size_t)n * DIN + lane];
        stage_x[w][lane] = h0;
        __syncwarp();

        const float cnt = g_cnt[n];
        float conv = g_agg[(size_t)n * DOUT + lane] / fmaxf(cnt, 1.f) + Bo[lane];
#pragma unroll
        for (int i = 0; i < 32; i++) conv += stage_x[w][i] * Rs[i * 32 + lane];

        const float c = (conv > 0.f) ? conv : expm1f(conv);
        stage_c[w][lane] = c;
        __syncwarp();

        float gr = Bi[lane], gz = Bi[32 + lane], gc = Bi[64 + lane];
        float hr = Bh[lane], hz = Bh[32 + lane], hc = Bh[64 + lane];
#pragma unroll
        for (int j = 0; j < 32; j++) {
            const float cj = stage_c[w][j];
            const float hj = stage_x[w][j];
            gr += cj * WiT[j * WP + lane];
            gz += cj * WiT[j * WP + 32 + lane];
            gc += cj * WiT[j * WP + 64 + lane];
            hr += hj * WhT[j * WP + lane];
            hz += hj * WhT[j * WP + 32 + lane];
            hc += hj * WhT[j * WP + 64 + lane];
        }

        const float r  = 1.f / (1.f + expf(-(gr + hr)));
        const float zg = 1.f / (1.f + expf(-(gz + hz)));
        const float nn = tanhf(gc + r * hc);
        const float h_new = (1.f - zg) * nn + zg * h0;

        out[(size_t)n * DOUT + lane] = fmaxf(h_new + h0, 0.f);
        if (write_h)
            out[(size_t)N_NODES * DOUT + (size_t)n * DOUT + lane] = h_new;
        __syncwarp();   // protect stage arrays before next iteration's writes
    }
}

// ============================================================
extern "C" void kernel_launch(void* const* d_in, const int* in_sizes, int n_in,
                              void* d_out, int out_size) {
    const float* x         = (const float*)d_in[0];
    const float* edge_attr = (const float*)d_in[1];
    const float* nn_w      = (const float*)d_in[2];
    const float* nn_b      = (const float*)d_in[3];
    const float* root      = (const float*)d_in[4];
    const float* bias      = (const float*)d_in[5];
    const float* w_ih      = (const float*)d_in[6];
    const float* w_hh      = (const float*)d_in[7];
    const float* b_ih      = (const float*)d_in[8];
    const float* b_hh      = (const float*)d_in[9];
    const int* edge_index  = (const int*)d_in[10];
    float* out = (float*)d_out;

    const int smemF = (32 * ZC + NODES_PER_BLK * ZPITCH) * (int)sizeof(float); // 173056
    cudaFuncSetAttribute(kFused, cudaFuncAttributeMaxDynamicSharedMemorySize, smemF);

    const int gridE = (N_EDGES + 255) / 256;

    kZero<<<512, 256>>>();
    kHist<<<gridE, 256>>>(edge_index);
    kScan1<<<NSCAN_BLKS, SCAN_BLK>>>();
    kScan2<<<1, 128>>>();
    kScan3<<<NSCAN_BLKS, SCAN_BLK>>>();
    kScat<<<gridE, 256>>>(edge_index);

    const int gridF = (N_NODES + NODES_PER_BLK - 1) / NODES_PER_BLK;  // 1563
    kFused<<<gridF, KF_THREADS, smemF>>>(x, nn_w, nn_b, edge_attr);

    const int write_h = (out_size >= 2 * N_NODES * DOUT) ? 1 : 0;
    k3_gru<<<GRID3, 256>>>(x, root, bias, w_ih, w_hh, b_ih, b_hh, out, write_h);
}

// round 5
// speedup vs baseline: 2.0112x; 1.0006x over previous
#include <cuda_runtime.h>
#include <math.h>
#include <stdint.h>

#define N_NODES 100000
#define N_EDGES 250000
#define DIN 32
#define DOUT 32
#define DE 13
#define ZC 448          // 14*32 z-columns (13 ea dims + 1 bias slot)
#define ZPITCH 452      // smem z row pitch (floats)
#define NODES_PER_BLK 64
#define NT 1563         // ceil(N_NODES/64) tiles
#define KF_THREADS 512
#define GRID3 888
#define WP 97           // padded transposed-weight pitch (conflict-free)
#define WBLKS 14        // weight-transpose blocks inside kHistW

// -------- scratch (device globals: zero-initialized at module load;
//          every kernel_launch invocation restores the zero invariant) -----
__device__ float g_agg[(size_t)N_NODES * DOUT];  // zeroed by k3 after read
__device__ float g_cnt[N_NODES];                 // zeroed by k3 after read
__device__ int   g_tcnt[NT];                     // zeroed by kScanT after read
__device__ int   g_toff[NT + 1];
__device__ int   g_tcur[NT];
__device__ int   g_epack[N_EDGES];               // (ls<<18) | eid
__device__ int   g_edst[N_EDGES];
__device__ float g_wbig[32 * ZC];                // pre-transposed Wbig

// ============================================================
// kHistW: (a) blocks [0,WBLKS): transpose nn_w/nn_b -> g_wbig
//         (b) remaining blocks: tile histogram + dst in-degree
// ============================================================
__global__ void kHistW(const int* __restrict__ ei,
                       const float* __restrict__ nn_w,
                       const float* __restrict__ nn_b) {
    const int b = blockIdx.x;
    const int t = threadIdx.x;
    if (b < WBLKS) {
        for (int idx = b * 256 + t; idx < 32 * ZC; idx += WBLKS * 256) {
            int i = idx / ZC;
            int c = idx - i * ZC;
            int d = c >> 5, o = c & 31;
            g_wbig[idx] = (d < 13) ? nn_w[(i * 32 + o) * 13 + d]
                                   : nn_b[i * 32 + o];
        }
    } else {
        int e = (b - WBLKS) * 256 + t;
        if (e < N_EDGES) {
            atomicAdd(&g_tcnt[ei[e] >> 6], 1);
            atomicAdd(&g_cnt[ei[N_EDGES + e]], 1.f);
        }
    }
}

// ============================================================
// kScanT: single block, exclusive scan of 1563 tile counts.
// Writes g_toff / g_tcur, re-zeroes g_tcnt (invariant).
// ============================================================
__global__ void kScanT() {
    __shared__ int wsum[32];
    __shared__ int carry;
    const int t = threadIdx.x;      // 1024
    const int lane = t & 31, w = t >> 5;
    if (t == 0) carry = 0;
    __syncthreads();

#pragma unroll
    for (int c = 0; c < 2; c++) {
        const int idx = c * 1024 + t;
        int v = (idx < NT) ? g_tcnt[idx] : 0;
        int s = v;
#pragma unroll
        for (int o = 1; o < 32; o <<= 1) {
            int u = __shfl_up_sync(0xffffffffu, s, o);
            if (lane >= o) s += u;
        }
        if (lane == 31) wsum[w] = s;
        __syncthreads();
        if (w == 0) {
            int ws = wsum[lane];
#pragma unroll
            for (int o = 1; o < 32; o <<= 1) {
                int u = __shfl_up_sync(0xffffffffu, ws, o);
                if (lane >= o) ws += u;
            }
            wsum[lane] = ws;
        }
        __syncthreads();
        const int excl = carry + (w > 0 ? wsum[w - 1] : 0) + s - v;
        if (idx < NT) {
            g_toff[idx] = excl;
            g_tcur[idx] = excl;
            g_tcnt[idx] = 0;        // restore zero invariant
        }
        __syncthreads();
        if (t == 0) carry += wsum[31];
        __syncthreads();
    }
    if (t == 0) g_toff[NT] = N_EDGES;
}

// ============================================================
// kScatT: scatter edges into tile-contiguous segments.
// ============================================================
__global__ void kScatT(const int* __restrict__ ei) {
    int e = blockIdx.x * blockDim.x + threadIdx.x;
    if (e >= N_EDGES) return;
    int src = ei[e];
    int dst = ei[N_EDGES + e];
    int pos = atomicAdd(&g_tcur[src >> 6], 1);
    g_epack[pos] = ((src & 63) << 18) | e;   // eid < 2^18
    g_edst[pos] = dst;
}

// ============================================================
// kFused: 64-node tile.
// Phase 1: z tile in SMEM (scalar FFMA GEMM, lane=node, warp=col octant).
// Phase 2: tile's contiguous edge segment, warp-strided RED scatter.
// ============================================================
__global__ void __launch_bounds__(KF_THREADS, 1)
kFused(const float* __restrict__ x,
       const float* __restrict__ edge_attr) {
    extern __shared__ __align__(16) float sm[];
    float* Ws = sm;               // [32][448] = 57344 B
    float* zs = sm + 32 * ZC;     // [64][452] = 115712 B

    const int t = threadIdx.x;    // 512 = 16 warps
    const int lane = t & 31;
    const int w = t >> 5;

    // coalesced weight staging from pre-transposed g_wbig
    {
        const float4* wsrc = (const float4*)g_wbig;
        float4* wdst = (float4*)Ws;
#pragma unroll
        for (int q = 0; q < 7; q++) wdst[t + q * KF_THREADS] = wsrc[t + q * KF_THREADS];
    }
    __syncthreads();

    // ---- phase 1: lane = node (2 halves of 32), warp covers 56 cols ----
    const int g  = w >> 3;
    const int cw = w & 7;
    const int ln = g * 32 + lane;
    const int n  = blockIdx.x * NODES_PER_BLK + ln;

    float xr[32];
    if (n < N_NODES) {
        const float4* xv = (const float4*)(x + (size_t)n * DIN);
#pragma unroll
        for (int q = 0; q < 8; q++) {
            float4 v = xv[q];
            xr[q * 4 + 0] = v.x; xr[q * 4 + 1] = v.y;
            xr[q * 4 + 2] = v.z; xr[q * 4 + 3] = v.w;
        }
    } else {
#pragma unroll
        for (int q = 0; q < 32; q++) xr[q] = 0.f;
    }

    float* zrow = zs + (size_t)ln * ZPITCH + cw * 56;

#pragma unroll 1
    for (int c = 0; c < 7; c++) {
        const int c0 = cw * 56 + c * 8;
        float acc[8];
#pragma unroll
        for (int q = 0; q < 8; q++) acc[q] = 0.f;

#pragma unroll
        for (int i = 0; i < 32; i++) {
            const float4* w4 = (const float4*)(Ws + i * ZC + c0);
            const float xi = xr[i];
            float4 wa = w4[0], wb = w4[1];
            acc[0] += xi * wa.x; acc[1] += xi * wa.y;
            acc[2] += xi * wa.z; acc[3] += xi * wa.w;
            acc[4] += xi * wb.x; acc[5] += xi * wb.y;
            acc[6] += xi * wb.z; acc[7] += xi * wb.w;
        }

        float4* zo = (float4*)(zrow + c * 8);
        zo[0] = make_float4(acc[0], acc[1], acc[2], acc[3]);
        zo[1] = make_float4(acc[4], acc[5], acc[6], acc[7]);
    }
    __syncthreads();

    // ---- phase 2: contiguous edge segment, warp-strided ----
    const int o0 = g_toff[blockIdx.x];
    const int o1 = g_toff[blockIdx.x + 1];

    for (int j = o0 + w; j < o1; j += 16) {
        const int pk  = g_epack[j];
        const int dst = g_edst[j];
        const int ls  = pk >> 18;
        const int eid = pk & 0x3FFFF;

        float a = (lane < DE) ? edge_attr[(size_t)eid * DE + lane] : 0.f;

        const float* zr = zs + (size_t)ls * ZPITCH;
        float msg = zr[13 * 32 + lane];
#pragma unroll
        for (int d = 0; d < DE; d++)
            msg += __shfl_sync(0xffffffffu, a, d) * zr[d * 32 + lane];

        atomicAdd(&g_agg[(size_t)dst * DOUT + lane], msg);
    }
}

// ============================================================
// k3: mean + root GEMV + bias -> CELU -> GRU -> residual ReLU.
// Grid-stride; restores zero invariant on g_agg / g_cnt.
// ============================================================
__global__ void __launch_bounds__(256)
k3_gru(const float* __restrict__ x,
       const float* __restrict__ root,
       const float* __restrict__ bias,
       const float* __restrict__ w_ih,
       const float* __restrict__ w_hh,
       const float* __restrict__ b_ih,
       const float* __restrict__ b_hh,
       float* __restrict__ out,
       int write_h) {
    __shared__ float Rs[DIN * DOUT];
    __shared__ float WiT[32 * WP];
    __shared__ float WhT[32 * WP];
    __shared__ float Bi[96], Bh[96], Bo[32];
    __shared__ float stage_x[8][32];
    __shared__ float stage_c[8][32];

    const int t = threadIdx.x;  // 256
    for (int idx = t; idx < DIN * DOUT; idx += 256) Rs[idx] = root[idx];
    for (int idx = t; idx < 96 * 32; idx += 256) {
        int g = idx >> 5, j = idx & 31;
        WiT[j * WP + g] = w_ih[idx];
        WhT[j * WP + g] = w_hh[idx];
    }
    if (t < 96) { Bi[t] = b_ih[t]; Bh[t] = b_hh[t]; }
    if (t < 32) Bo[t] = bias[t];
    __syncthreads();

    const int w = t >> 5;
    const int lane = t & 31;

    for (int n = blockIdx.x * 8 + w; n < N_NODES; n += GRID3 * 8) {
        const float h0 = x[(size_t)n * DIN + lane];
        stage_x[w][lane] = h0;
        __syncwarp();

        const float cnt = g_cnt[n];
        const float aggv = g_agg[(size_t)n * DOUT + lane];
        g_agg[(size_t)n * DOUT + lane] = 0.f;   // restore zero invariant

        float conv = aggv / fmaxf(cnt, 1.f) + Bo[lane];
#pragma unroll
        for (int i = 0; i < 32; i++) conv += stage_x[w][i] * Rs[i * 32 + lane];

        const float c = (conv > 0.f) ? conv : expm1f(conv);
        stage_c[w][lane] = c;
        __syncwarp();

        float gr = Bi[lane], gz = Bi[32 + lane], gc = Bi[64 + lane];
        float hr = Bh[lane], hz = Bh[32 + lane], hc = Bh[64 + lane];
#pragma unroll
        for (int j = 0; j < 32; j++) {
            const float cj = stage_c[w][j];
            const float hj = stage_x[w][j];
            gr += cj * WiT[j * WP + lane];
            gz += cj * WiT[j * WP + 32 + lane];
            gc += cj * WiT[j * WP + 64 + lane];
            hr += hj * WhT[j * WP + lane];
            hz += hj * WhT[j * WP + 32 + lane];
            hc += hj * WhT[j * WP + 64 + lane];
        }

        const float r  = 1.f / (1.f + expf(-(gr + hr)));
        const float zg = 1.f / (1.f + expf(-(gz + hz)));
        const float nn = tanhf(gc + r * hc);
        const float h_new = (1.f - zg) * nn + zg * h0;

        out[(size_t)n * DOUT + lane] = fmaxf(h_new + h0, 0.f);
        if (write_h)
            out[(size_t)N_NODES * DOUT + (size_t)n * DOUT + lane] = h_new;
        __syncwarp();                   // cnt reads done across warp
        if (lane == 0) g_cnt[n] = 0.f;  // restore zero invariant
        __syncwarp();                   // protect stage arrays for next iter
    }
}

// ============================================================
extern "C" void kernel_launch(void* const* d_in, const int* in_sizes, int n_in,
                              void* d_out, int out_size) {
    const float* x         = (const float*)d_in[0];
    const float* edge_attr = (const float*)d_in[1];
    const float* nn_w      = (const float*)d_in[2];
    const float* nn_b      = (const float*)d_in[3];
    const float* root      = (const float*)d_in[4];
    const float* bias      = (const float*)d_in[5];
    const float* w_ih      = (const float*)d_in[6];
    const float* w_hh      = (const float*)d_in[7];
    const float* b_ih      = (const float*)d_in[8];
    const float* b_hh      = (const float*)d_in[9];
    const int* edge_index  = (const int*)d_in[10];
    float* out = (float*)d_out;

    const int smemF = (32 * ZC + NODES_PER_BLK * ZPITCH) * (int)sizeof(float); // 173056
    cudaFuncSetAttribute(kFused, cudaFuncAttributeMaxDynamicSharedMemorySize, smemF);

    const int gridE = (N_EDGES + 255) / 256;      // 977

    kHistW<<<WBLKS + gridE, 256>>>(edge_index, nn_w, nn_b);   // launch 1
    kScanT<<<1, 1024>>>();                                    // launch 2
    kScatT<<<gridE, 256>>>(edge_index);                       // launch 3
    kFused<<<NT, KF_THREADS, smemF>>>(x, edge_attr);          // launch 4
    const int write_h = (out_size >= 2 * N_NODES * DOUT) ? 1 : 0;
    k3_gru<<<GRID3, 256>>>(x, root, bias, w_ih, w_hh, b_ih, b_hh, out, write_h); // 5
}

// round 6
// speedup vs baseline: 2.0754x; 1.0319x over previous
#include <cuda_runtime.h>
#include <math.h>
#include <stdint.h>

#define N_NODES 100000
#define N_EDGES 250000
#define DIN 32
#define DOUT 32
#define DE 13
#define ZC 448          // 14*32 z-columns (13 ea dims + 1 bias slot)
#define ZPITCH 452      // smem z row pitch (floats)
#define NODES_PER_BLK 64
#define NT 1563         // ceil(N_NODES/64) tiles
#define KF_THREADS 512
#define GRID3 888
#define WP 97           // padded transposed-weight pitch (conflict-free)
#define WBLKS 14        // weight-transpose blocks inside kHistW

// -------- scratch (device globals: zero-initialized at module load;
//          every kernel_launch invocation restores the zero invariant) -----
__device__ float g_agg[(size_t)N_NODES * DOUT];  // zeroed by k3 after read
__device__ float g_cnt[N_NODES];                 // zeroed by k3 after read
__device__ int   g_tcnt[NT];                     // zeroed by kScanT after read
__device__ int   g_toff[NT + 1];
__device__ int   g_tcur[NT];
__device__ int   g_epack[N_EDGES];               // (ls<<18) | eid
__device__ int   g_edst[N_EDGES];
__device__ float g_wbig[32 * ZC];                // pre-transposed Wbig

// -------- packed f32x2 helpers --------
__device__ __forceinline__ uint64_t pk2(float a, float b) {
    uint64_t r; asm("mov.b64 %0, {%1, %2};" : "=l"(r) : "f"(a), "f"(b)); return r;
}
__device__ __forceinline__ void fma2(uint64_t& d, uint64_t a, uint64_t b) {
    asm("fma.rn.f32x2 %0, %1, %2, %0;" : "+l"(d) : "l"(a), "l"(b));
}

// ============================================================
// kHistW: (a) blocks [0,WBLKS): transpose nn_w/nn_b -> g_wbig
//         (b) remaining blocks: tile histogram + dst in-degree
// ============================================================
__global__ void kHistW(const int* __restrict__ ei,
                       const float* __restrict__ nn_w,
                       const float* __restrict__ nn_b) {
    const int b = blockIdx.x;
    const int t = threadIdx.x;
    if (b < WBLKS) {
        for (int idx = b * 256 + t; idx < 32 * ZC; idx += WBLKS * 256) {
            int i = idx / ZC;
            int c = idx - i * ZC;
            int d = c >> 5, o = c & 31;
            g_wbig[idx] = (d < 13) ? nn_w[(i * 32 + o) * 13 + d]
                                   : nn_b[i * 32 + o];
        }
    } else {
        int e = (b - WBLKS) * 256 + t;
        if (e < N_EDGES) {
            atomicAdd(&g_tcnt[ei[e] >> 6], 1);
            atomicAdd(&g_cnt[ei[N_EDGES + e]], 1.f);
        }
    }
}

// ============================================================
// kScanT: single block, exclusive scan of 1563 tile counts.
// ============================================================
__global__ void kScanT() {
    __shared__ int wsum[32];
    __shared__ int carry;
    const int t = threadIdx.x;      // 1024
    const int lane = t & 31, w = t >> 5;
    if (t == 0) carry = 0;
    __syncthreads();

#pragma unroll
    for (int c = 0; c < 2; c++) {
        const int idx = c * 1024 + t;
        int v = (idx < NT) ? g_tcnt[idx] : 0;
        int s = v;
#pragma unroll
        for (int o = 1; o < 32; o <<= 1) {
            int u = __shfl_up_sync(0xffffffffu, s, o);
            if (lane >= o) s += u;
        }
        if (lane == 31) wsum[w] = s;
        __syncthreads();
        if (w == 0) {
            int ws = wsum[lane];
#pragma unroll
            for (int o = 1; o < 32; o <<= 1) {
                int u = __shfl_up_sync(0xffffffffu, ws, o);
                if (lane >= o) ws += u;
            }
            wsum[lane] = ws;
        }
        __syncthreads();
        const int excl = carry + (w > 0 ? wsum[w - 1] : 0) + s - v;
        if (idx < NT) {
            g_toff[idx] = excl;
            g_tcur[idx] = excl;
            g_tcnt[idx] = 0;        // restore zero invariant
        }
        __syncthreads();
        if (t == 0) carry += wsum[31];
        __syncthreads();
    }
    if (t == 0) g_toff[NT] = N_EDGES;
}

// ============================================================
// kScatT: scatter edges into tile-contiguous segments.
// ============================================================
__global__ void kScatT(const int* __restrict__ ei) {
    int e = blockIdx.x * blockDim.x + threadIdx.x;
    if (e >= N_EDGES) return;
    int src = ei[e];
    int dst = ei[N_EDGES + e];
    int pos = atomicAdd(&g_tcur[src >> 6], 1);
    g_epack[pos] = ((src & 63) << 18) | e;   // eid < 2^18
    g_edst[pos] = dst;
}

// ============================================================
// kFused: 64-node tile.
// Phase 1: z tile in SMEM — packed f32x2 GEMM over column pairs:
//   acc pairs come straight out of LDS.128 W loads (no repacking),
//   x duplicated with one mov.b64 per i. Halves fp32-pipe issue.
// Phase 2: tile's contiguous edge segment, warp-strided,
//   software-pipelined (prefetch next edge while reducing current).
// ============================================================
__global__ void __launch_bounds__(KF_THREADS, 1)
kFused(const float* __restrict__ x,
       const float* __restrict__ edge_attr) {
    extern __shared__ __align__(16) float sm[];
    float* Ws = sm;               // [32][448] = 57344 B
    float* zs = sm + 32 * ZC;     // [64][452] = 115712 B

    const int t = threadIdx.x;    // 512 = 16 warps
    const int lane = t & 31;
    const int w = t >> 5;

    // coalesced weight staging from pre-transposed g_wbig
    {
        const float4* wsrc = (const float4*)g_wbig;
        float4* wdst = (float4*)Ws;
#pragma unroll
        for (int q = 0; q < 7; q++) wdst[t + q * KF_THREADS] = wsrc[t + q * KF_THREADS];
    }
    __syncthreads();

    // ---- phase 1: lane = node (2 halves of 32), warp covers 56 cols ----
    const int g  = w >> 3;
    const int cw = w & 7;
    const int ln = g * 32 + lane;
    const int n  = blockIdx.x * NODES_PER_BLK + ln;

    float xr[32];
    if (n < N_NODES) {
        const float4* xv = (const float4*)(x + (size_t)n * DIN);
#pragma unroll
        for (int q = 0; q < 8; q++) {
            float4 v = xv[q];
            xr[q * 4 + 0] = v.x; xr[q * 4 + 1] = v.y;
            xr[q * 4 + 2] = v.z; xr[q * 4 + 3] = v.w;
        }
    } else {
#pragma unroll
        for (int q = 0; q < 32; q++) xr[q] = 0.f;
    }

    float* zrow = zs + (size_t)ln * ZPITCH + cw * 56;

#pragma unroll 1
    for (int c = 0; c < 7; c++) {          // 7 chunks of 8 cols = 4 col-pairs
        const int c0 = cw * 56 + c * 8;
        uint64_t acc[4];
#pragma unroll
        for (int q = 0; q < 4; q++) acc[q] = 0ull;

#pragma unroll
        for (int i = 0; i < 32; i++) {
            const ulonglong2* w2 = (const ulonglong2*)(Ws + i * ZC + c0);
            ulonglong2 wa = w2[0], wb = w2[1];          // 2x LDS.128
            const uint64_t xp = pk2(xr[i], xr[i]);       // 1 mov.b64
            fma2(acc[0], xp, wa.x);                      // 4x FFMA2
            fma2(acc[1], xp, wa.y);
            fma2(acc[2], xp, wb.x);
            fma2(acc[3], xp, wb.y);
        }

        ulonglong2* zo = (ulonglong2*)(zrow + c * 8);
        ulonglong2 s0, s1;
        s0.x = acc[0]; s0.y = acc[1];
        s1.x = acc[2]; s1.y = acc[3];
        zo[0] = s0; zo[1] = s1;
    }
    __syncthreads();

    // ---- phase 2: contiguous edge segment, warp-strided, pipelined ----
    const int o0 = g_toff[blockIdx.x];
    const int o1 = g_toff[blockIdx.x + 1];

    int j = o0 + w;
    if (j < o1) {
        int pk  = __ldg(&g_epack[j]);
        int dst = __ldg(&g_edst[j]);
        float a = (lane < DE)
                ? __ldg(&edge_attr[(size_t)(pk & 0x3FFFF) * DE + lane]) : 0.f;

        while (j < o1) {
            const int jn = j + 16;
            int pkn = 0, dstn = 0; float an = 0.f;
            if (jn < o1) {
                pkn  = __ldg(&g_epack[jn]);
                dstn = __ldg(&g_edst[jn]);
                an = (lane < DE)
                   ? __ldg(&edge_attr[(size_t)(pkn & 0x3FFFF) * DE + lane]) : 0.f;
            }

            const int ls = pk >> 18;
            const float* zr = zs + (size_t)ls * ZPITCH;
            float msg = zr[13 * 32 + lane];
#pragma unroll
            for (int d = 0; d < DE; d++)
                msg += __shfl_sync(0xffffffffu, a, d) * zr[d * 32 + lane];

            atomicAdd(&g_agg[(size_t)dst * DOUT + lane], msg);

            j = jn; pk = pkn; dst = dstn; a = an;
        }
    }
}

// ============================================================
// k3: mean + root GEMV + bias -> CELU -> GRU -> residual ReLU.
// Grid-stride; restores zero invariant on g_agg / g_cnt.
// ============================================================
__global__ void __launch_bounds__(256)
k3_gru(const float* __restrict__ x,
       const float* __restrict__ root,
       const float* __restrict__ bias,
       const float* __restrict__ w_ih,
       const float* __restrict__ w_hh,
       const float* __restrict__ b_ih,
       const float* __restrict__ b_hh,
       float* __restrict__ out,
       int write_h) {
    __shared__ float Rs[DIN * DOUT];
    __shared__ float WiT[32 * WP];
    __shared__ float WhT[32 * WP];
    __shared__ float Bi[96], Bh[96], Bo[32];
    __shared__ float stage_x[8][32];
    __shared__ float stage_c[8][32];

    const int t = threadIdx.x;  // 256
    for (int idx = t; idx < DIN * DOUT; idx += 256) Rs[idx] = root[idx];
    for (int idx = t; idx < 96 * 32; idx += 256) {
        int g = idx >> 5, j = idx & 31;
        WiT[j * WP + g] = w_ih[idx];
        WhT[j * WP + g] = w_hh[idx];
    }
    if (t < 96) { Bi[t] = b_ih[t]; Bh[t] = b_hh[t]; }
    if (t < 32) Bo[t] = bias[t];
    __syncthreads();

    const int w = t >> 5;
    const int lane = t & 31;

    for (int n = blockIdx.x * 8 + w; n < N_NODES; n += GRID3 * 8) {
        const float h0 = x[(size_t)n * DIN + lane];
        stage_x[w][lane] = h0;
        __syncwarp();

        const float cnt = g_cnt[n];
        const float aggv = g_agg[(size_t)n * DOUT + lane];
        g_agg[(size_t)n * DOUT + lane] = 0.f;   // restore zero invariant

        float conv = aggv / fmaxf(cnt, 1.f) + Bo[lane];
#pragma unroll
        for (int i = 0; i < 32; i++) conv += stage_x[w][i] * Rs[i * 32 + lane];

        const float c = (conv > 0.f) ? conv : expm1f(conv);
        stage_c[w][lane] = c;
        __syncwarp();

        float gr = Bi[lane], gz = Bi[32 + lane], gc = Bi[64 + lane];
        float hr = Bh[lane], hz = Bh[32 + lane], hc = Bh[64 + lane];
#pragma unroll
        for (int j = 0; j < 32; j++) {
            const float cj = stage_c[w][j];
            const float hj = stage_x[w][j];
            gr += cj * WiT[j * WP + lane];
            gz += cj * WiT[j * WP + 32 + lane];
            gc += cj * WiT[j * WP + 64 + lane];
            hr += hj * WhT[j * WP + lane];
            hz += hj * WhT[j * WP + 32 + lane];
            hc += hj * WhT[j * WP + 64 + lane];
        }

        const float r  = 1.f / (1.f + expf(-(gr + hr)));
        const float zg = 1.f / (1.f + expf(-(gz + hz)));
        const float nn = tanhf(gc + r * hc);
        const float h_new = (1.f - zg) * nn + zg * h0;

        out[(size_t)n * DOUT + lane] = fmaxf(h_new + h0, 0.f);
        if (write_h)
            out[(size_t)N_NODES * DOUT + (size_t)n * DOUT + lane] = h_new;
        __syncwarp();                   // cnt reads done across warp
        if (lane == 0) g_cnt[n] = 0.f;  // restore zero invariant
        __syncwarp();                   // protect stage arrays for next iter
    }
}

// ============================================================
extern "C" void kernel_launch(void* const* d_in, const int* in_sizes, int n_in,
                              void* d_out, int out_size) {
    const float* x         = (const float*)d_in[0];
    const float* edge_attr = (const float*)d_in[1];
    const float* nn_w      = (const float*)d_in[2];
    const float* nn_b      = (const float*)d_in[3];
    const float* root      = (const float*)d_in[4];
    const float* bias      = (const float*)d_in[5];
    const float* w_ih      = (const float*)d_in[6];
    const float* w_hh      = (const float*)d_in[7];
    const float* b_ih      = (const float*)d_in[8];
    const float* b_hh      = (const float*)d_in[9];
    const int* edge_index  = (const int*)d_in[10];
    float* out = (float*)d_out;

    const int smemF = (32 * ZC + NODES_PER_BLK * ZPITCH) * (int)sizeof(float); // 173056
    cudaFuncSetAttribute(kFused, cudaFuncAttributeMaxDynamicSharedMemorySize, smemF);

    const int gridE = (N_EDGES + 255) / 256;      // 977

    kHistW<<<WBLKS + gridE, 256>>>(edge_index, nn_w, nn_b);   // launch 1
    kScanT<<<1, 1024>>>();                                    // launch 2
    kScatT<<<gridE, 256>>>(edge_index);                       // launch 3
    kFused<<<NT, KF_THREADS, smemF>>>(x, edge_attr);          // launch 4
    const int write_h = (out_size >= 2 * N_NODES * DOUT) ? 1 : 0;
    k3_gru<<<GRID3, 256>>>(x, root, bias, w_ih, w_hh, b_ih, b_hh, out, write_h); // 5
}

// round 7
// speedup vs baseline: 2.4204x; 1.1662x over previous
#include <cuda_runtime.h>
#include <math.h>
#include <stdint.h>

#define N_NODES 100000
#define N_EDGES 250000
#define DIN 32
#define DOUT 32
#define DE 13
#define ZC 448          // 14*32 z-columns (13 ea dims + 1 bias slot)
#define ZPITCH 456      // smem z row pitch (floats)
#define XPITCH 68       // transposed x tile pitch
#define NODES_PER_BLK 64
#define NT 1563         // ceil(N_NODES/64) tiles
#define KF_THREADS 448  // 14 warps
#define GRID3 888
#define WP 97           // padded transposed-weight pitch (conflict-free)
#define WBLKS 14        // weight-transpose blocks inside kHistW

// -------- scratch (device globals: zero-initialized at module load;
//          every kernel_launch invocation restores the zero invariant) -----
__device__ float g_agg[(size_t)N_NODES * DOUT];  // zeroed by k3 after read
__device__ float g_cnt[N_NODES];                 // zeroed by k3 after read
__device__ int   g_tcnt[NT];                     // zeroed by kScanT after read
__device__ int   g_toff[NT + 1];
__device__ int   g_tcur[NT];
__device__ int   g_epack[N_EDGES];               // (ls<<18) | eid
__device__ int   g_edst[N_EDGES];
__device__ float g_wbig[32 * ZC];                // pre-transposed Wbig

// -------- packed f32x2 helpers --------
__device__ __forceinline__ uint64_t pk2(float a, float b) {
    uint64_t r; asm("mov.b64 %0, {%1, %2};" : "=l"(r) : "f"(a), "f"(b)); return r;
}
__device__ __forceinline__ void unpk(uint64_t v, float& a, float& b) {
    asm("mov.b64 {%0, %1}, %2;" : "=f"(a), "=f"(b) : "l"(v));
}
__device__ __forceinline__ void fma2(uint64_t& d, uint64_t a, uint64_t b) {
    asm("fma.rn.f32x2 %0, %1, %2, %0;" : "+l"(d) : "l"(a), "l"(b));
}

// ============================================================
// kHistW: (a) blocks [0,WBLKS): transpose nn_w/nn_b -> g_wbig
//         (b) remaining blocks: tile histogram + dst in-degree
// ============================================================
__global__ void kHistW(const int* __restrict__ ei,
                       const float* __restrict__ nn_w,
                       const float* __restrict__ nn_b) {
    const int b = blockIdx.x;
    const int t = threadIdx.x;
    if (b < WBLKS) {
        for (int idx = b * 256 + t; idx < 32 * ZC; idx += WBLKS * 256) {
            int i = idx / ZC;
            int c = idx - i * ZC;
            int d = c >> 5, o = c & 31;
            g_wbig[idx] = (d < 13) ? nn_w[(i * 32 + o) * 13 + d]
                                   : nn_b[i * 32 + o];
        }
    } else {
        int e = (b - WBLKS) * 256 + t;
        if (e < N_EDGES) {
            atomicAdd(&g_tcnt[ei[e] >> 6], 1);
            atomicAdd(&g_cnt[ei[N_EDGES + e]], 1.f);
        }
    }
}

// ============================================================
// kScanT: single block, exclusive scan of 1563 tile counts.
// ============================================================
__global__ void kScanT() {
    __shared__ int wsum[32];
    __shared__ int carry;
    const int t = threadIdx.x;      // 1024
    const int lane = t & 31, w = t >> 5;
    if (t == 0) carry = 0;
    __syncthreads();

#pragma unroll
    for (int c = 0; c < 2; c++) {
        const int idx = c * 1024 + t;
        int v = (idx < NT) ? g_tcnt[idx] : 0;
        int s = v;
#pragma unroll
        for (int o = 1; o < 32; o <<= 1) {
            int u = __shfl_up_sync(0xffffffffu, s, o);
            if (lane >= o) s += u;
        }
        if (lane == 31) wsum[w] = s;
        __syncthreads();
        if (w == 0) {
            int ws = wsum[lane];
#pragma unroll
            for (int o = 1; o < 32; o <<= 1) {
                int u = __shfl_up_sync(0xffffffffu, ws, o);
                if (lane >= o) ws += u;
            }
            wsum[lane] = ws;
        }
        __syncthreads();
        const int excl = carry + (w > 0 ? wsum[w - 1] : 0) + s - v;
        if (idx < NT) {
            g_toff[idx] = excl;
            g_tcur[idx] = excl;
            g_tcnt[idx] = 0;        // restore zero invariant
        }
        __syncthreads();
        if (t == 0) carry += wsum[31];
        __syncthreads();
    }
    if (t == 0) g_toff[NT] = N_EDGES;
}

// ============================================================
// kScatT: scatter edges into tile-contiguous segments.
// ============================================================
__global__ void kScatT(const int* __restrict__ ei) {
    int e = blockIdx.x * blockDim.x + threadIdx.x;
    if (e >= N_EDGES) return;
    int src = ei[e];
    int dst = ei[N_EDGES + e];
    int pos = atomicAdd(&g_tcur[src >> 6], 1);
    g_epack[pos] = ((src & 63) << 18) | e;   // eid < 2^18
    g_edst[pos] = dst;
}

// ============================================================
// kFused: 64-node tile.
// Phase 1: register-tiled f32x2 GEMM — thread computes 8 nodes x 8 cols.
//   x from transposed smem tile (distinct-data LDS.128), W streamed
//   (distinct-data LDS.128). z stored with per-node-octet column rotation
//   (col' = (c + 2*(n>>3 & 3)) & 63 within each 64-col block) to kill
//   store bank conflicts; phase 2 applies the same rotation on read.
// Phase 2: tile's contiguous edge segment, warp-strided, pipelined.
// ============================================================
__global__ void __launch_bounds__(KF_THREADS, 1)
kFused(const float* __restrict__ x,
       const float* __restrict__ edge_attr) {
    extern __shared__ __align__(16) float sm[];
    float* Ws = sm;                         // [32][448]   57344 B
    float* zs = sm + 32 * ZC;               // [64][456]  116736 B
    float* xT = zs + NODES_PER_BLK * ZPITCH; // [32][68]     8704 B

    const int t = threadIdx.x;    // 448 = 14 warps
    const int lane = t & 31;
    const int w = t >> 5;

    // stage weights (coalesced, distinct data)
    {
        const float4* wsrc = (const float4*)g_wbig;
        float4* wdst = (float4*)Ws;
#pragma unroll
        for (int q = 0; q < 8; q++) wdst[t + q * KF_THREADS] = wsrc[t + q * KF_THREADS];
    }

    // stage transposed x tile: xT[i][n_local]
    const int nbase = blockIdx.x * NODES_PER_BLK;
#pragma unroll
    for (int idx = t; idx < NODES_PER_BLK * 32; idx += KF_THREADS) {
        int nl = idx >> 5, i = idx & 31;
        float v = (nbase + nl < N_NODES) ? x[(size_t)(nbase + nl) * DIN + i] : 0.f;
        xT[i * XPITCH + nl] = v;
    }
    __syncthreads();

    // ---- phase 1: warp = (node-half, 64-col block); thread = 8n x 8c ----
    const int h  = w / 7;                 // node half (0/1)
    const int cb = w % 7;                 // 64-col block (0..6)
    const int no = lane >> 3;             // node octet within half (0..3)
    const int co = lane & 7;              // col octet within block (0..7)
    const int bn = h * 32 + no * 8;       // local node base
    const int bc = cb * 64 + co * 8;      // col base
    const int rot = 2 * no;               // column rotation for this node octet

    uint64_t acc[32];                     // acc[j*4+p] = (col bc+2p, bc+2p+1), node bn+j
#pragma unroll
    for (int q = 0; q < 32; q++) acc[q] = 0ull;

#pragma unroll 8
    for (int i = 0; i < 32; i++) {
        const ulonglong2* xv = (const ulonglong2*)(xT + i * XPITCH + bn);
        const ulonglong2* wv = (const ulonglong2*)(Ws + i * ZC + bc);
        ulonglong2 xa = xv[0], xb = xv[1];   // x[bn..bn+7] at feature i
        ulonglong2 wa = wv[0], wb = wv[1];   // W[i][bc..bc+7]

        float f0, f1, f2, f3, f4, f5, f6, f7;
        unpk(xa.x, f0, f1); unpk(xa.y, f2, f3);
        unpk(xb.x, f4, f5); unpk(xb.y, f6, f7);
        uint64_t xp[8];
        xp[0] = pk2(f0, f0); xp[1] = pk2(f1, f1);
        xp[2] = pk2(f2, f2); xp[3] = pk2(f3, f3);
        xp[4] = pk2(f4, f4); xp[5] = pk2(f5, f5);
        xp[6] = pk2(f6, f6); xp[7] = pk2(f7, f7);

#pragma unroll
        for (int j = 0; j < 8; j++) {
            fma2(acc[j * 4 + 0], xp[j], wa.x);
            fma2(acc[j * 4 + 1], xp[j], wa.y);
            fma2(acc[j * 4 + 2], xp[j], wb.x);
            fma2(acc[j * 4 + 3], xp[j], wb.y);
        }
    }

    // store z with rotated columns (conflict-minimal STS.64)
#pragma unroll
    for (int j = 0; j < 8; j++) {
        float* zr = zs + (size_t)(bn + j) * ZPITCH + cb * 64;
#pragma unroll
        for (int p = 0; p < 4; p++) {
            const int cl = (co * 8 + 2 * p + rot) & 63;   // even, never 63
            *(uint64_t*)(zr + cl) = acc[j * 4 + p];
        }
    }
    __syncthreads();

    // ---- phase 2: contiguous edge segment, warp-strided, pipelined ----
    const int o0 = g_toff[blockIdx.x];
    const int o1 = g_toff[blockIdx.x + 1];

    int j = o0 + w;
    if (j < o1) {
        int pk  = __ldg(&g_epack[j]);
        int dst = __ldg(&g_edst[j]);
        float a = (lane < DE)
                ? __ldg(&edge_attr[(size_t)(pk & 0x3FFFF) * DE + lane]) : 0.f;

        while (j < o1) {
            const int jn = j + 14;
            int pkn = 0, dstn = 0; float an = 0.f;
            if (jn < o1) {
                pkn  = __ldg(&g_epack[jn]);
                dstn = __ldg(&g_edst[jn]);
                an = (lane < DE)
                   ? __ldg(&edge_attr[(size_t)(pkn & 0x3FFFF) * DE + lane]) : 0.f;
            }

            const int ls = pk >> 18;
            const float* zr = zs + (size_t)ls * ZPITCH;
            const int rotE = 2 * ((ls >> 3) & 3);
            const int loA = lane + rotE;              // < 64, no mask needed
            const int loB = (32 + lane + rotE) & 63;

            // bias slot: logical col 416+lane -> block 6, upper half
            float msg = zr[6 * 64 + loB];
#pragma unroll
            for (int d = 0; d < DE; d++) {
                const float ad = __shfl_sync(0xffffffffu, a, d);
                const int off = (d >> 1) * 64 + ((d & 1) ? loB : loA);
                msg += ad * zr[off];
            }

            atomicAdd(&g_agg[(size_t)dst * DOUT + lane], msg);

            j = jn; pk = pkn; dst = dstn; a = an;
        }
    }
}

// ============================================================
// k3: mean + root GEMV + bias -> CELU -> GRU -> residual ReLU.
// Grid-stride; restores zero invariant on g_agg / g_cnt.
// ============================================================
__global__ void __launch_bounds__(256)
k3_gru(const float* __restrict__ x,
       const float* __restrict__ root,
       const float* __restrict__ bias,
       const float* __restrict__ w_ih,
       const float* __restrict__ w_hh,
       const float* __restrict__ b_ih,
       const float* __restrict__ b_hh,
       float* __restrict__ out,
       int write_h) {
    __shared__ float Rs[DIN * DOUT];
    __shared__ float WiT[32 * WP];
    __shared__ float WhT[32 * WP];
    __shared__ float Bi[96], Bh[96], Bo[32];
    __shared__ float stage_x[8][32];
    __shared__ float stage_c[8][32];

    const int t = threadIdx.x;  // 256
    for (int idx = t; idx < DIN * DOUT; idx += 256) Rs[idx] = root[idx];
    for (int idx = t; idx < 96 * 32; idx += 256) {
        int g = idx >> 5, j = idx & 31;
        WiT[j * WP + g] = w_ih[idx];
        WhT[j * WP + g] = w_hh[idx];
    }
    if (t < 96) { Bi[t] = b_ih[t]; Bh[t] = b_hh[t]; }
    if (t < 32) Bo[t] = bias[t];
    __syncthreads();

    const int w = t >> 5;
    const int lane = t & 31;

    for (int n = blockIdx.x * 8 + w; n < N_NODES; n += GRID3 * 8) {
        const float h0 = x[(size_t)n * DIN + lane];
        stage_x[w][lane] = h0;
        __syncwarp();

        const float cnt = g_cnt[n];
        const float aggv = g_agg[(size_t)n * DOUT + lane];
        g_agg[(size_t)n * DOUT + lane] = 0.f;   // restore zero invariant

        float conv = aggv / fmaxf(cnt, 1.f) + Bo[lane];
#pragma unroll
        for (int i = 0; i < 32; i++) conv += stage_x[w][i] * Rs[i * 32 + lane];

        const float c = (conv > 0.f) ? conv : expm1f(conv);
        stage_c[w][lane] = c;
        __syncwarp();

        float gr = Bi[lane], gz = Bi[32 + lane], gc = Bi[64 + lane];
        float hr = Bh[lane], hz = Bh[32 + lane], hc = Bh[64 + lane];
#pragma unroll
        for (int j = 0; j < 32; j++) {
            const float cj = stage_c[w][j];
            const float hj = stage_x[w][j];
            gr += cj * WiT[j * WP + lane];
            gz += cj * WiT[j * WP + 32 + lane];
            gc += cj * WiT[j * WP + 64 + lane];
            hr += hj * WhT[j * WP + lane];
            hz += hj * WhT[j * WP + 32 + lane];
            hc += hj * WhT[j * WP + 64 + lane];
        }

        const float r  = 1.f / (1.f + expf(-(gr + hr)));
        const float zg = 1.f / (1.f + expf(-(gz + hz)));
        const float nn = tanhf(gc + r * hc);
        const float h_new = (1.f - zg) * nn + zg * h0;

        out[(size_t)n * DOUT + lane] = fmaxf(h_new + h0, 0.f);
        if (write_h)
            out[(size_t)N_NODES * DOUT + (size_t)n * DOUT + lane] = h_new;
        __syncwarp();                   // cnt reads done across warp
        if (lane == 0) g_cnt[n] = 0.f;  // restore zero invariant
        __syncwarp();                   // protect stage arrays for next iter
    }
}

// ============================================================
extern "C" void kernel_launch(void* const* d_in, const int* in_sizes, int n_in,
                              void* d_out, int out_size) {
    const float* x         = (const float*)d_in[0];
    const float* edge_attr = (const float*)d_in[1];
    const float* nn_w      = (const float*)d_in[2];
    const float* nn_b      = (const float*)d_in[3];
    const float* root      = (const float*)d_in[4];
    const float* bias      = (const float*)d_in[5];
    const float* w_ih      = (const float*)d_in[6];
    const float* w_hh      = (const float*)d_in[7];
    const float* b_ih      = (const float*)d_in[8];
    const float* b_hh      = (const float*)d_in[9];
    const int* edge_index  = (const int*)d_in[10];
    float* out = (float*)d_out;

    const int smemF = (32 * ZC + NODES_PER_BLK * ZPITCH + 32 * XPITCH)
                      * (int)sizeof(float);   // 182784 B
    cudaFuncSetAttribute(kFused, cudaFuncAttributeMaxDynamicSharedMemorySize, smemF);

    const int gridE = (N_EDGES + 255) / 256;      // 977

    kHistW<<<WBLKS + gridE, 256>>>(edge_index, nn_w, nn_b);   // launch 1
    kScanT<<<1, 1024>>>();                                    // launch 2
    kScatT<<<gridE, 256>>>(edge_index);                       // launch 3
    kFused<<<NT, KF_THREADS, smemF>>>(x, edge_attr);          // launch 4
    const int write_h = (out_size >= 2 * N_NODES * DOUT) ? 1 : 0;
    k3_gru<<<GRID3, 256>>>(x, root, bias, w_ih, w_hh, b_ih, b_hh, out, write_h); // 5
}

// round 8
// speedup vs baseline: 2.7347x; 1.1299x over previous
#include <cuda_runtime.h>
#include <math.h>
#include <stdint.h>

#define N_NODES 100000
#define N_EDGES 250000
#define DIN 32
#define DOUT 32
#define DE 13
#define ZC 448          // 14*32 z-columns (13 ea dims + 1 bias slot)
#define ZPITCH 452      // smem z row pitch (floats)
#define XDP 68          // duplicated-x row pitch (floats): 64 data + 4 pad
#define NODES_PER_BLK 32
#define NT 3125         // N_NODES / 32 exactly
#define KF_THREADS 448  // 14 warps = 14 col-blocks of 32
#define GRID3 888
#define WP 97           // padded transposed-weight pitch (conflict-free)
#define WBLKS 14        // weight-transpose blocks inside kHistW

// -------- scratch (device globals: zero-initialized at module load;
//          every kernel_launch invocation restores the zero invariant) -----
__device__ float g_agg[(size_t)N_NODES * DOUT];  // zeroed by k3 after read
__device__ float g_cnt[N_NODES];                 // zeroed by k3 after read
__device__ int   g_tcnt[NT];                     // zeroed by kScanT after read
__device__ int   g_toff[NT + 1];
__device__ int   g_tcur[NT];
__device__ int   g_epack[N_EDGES];               // (ls<<18) | eid
__device__ int   g_edst[N_EDGES];
__device__ float g_wbig[32 * ZC];                // pre-transposed Wbig

// -------- packed f32x2 helpers --------
__device__ __forceinline__ uint64_t pk2(float a, float b) {
    uint64_t r; asm("mov.b64 %0, {%1, %2};" : "=l"(r) : "f"(a), "f"(b)); return r;
}
__device__ __forceinline__ void fma2(uint64_t& d, uint64_t a, uint64_t b) {
    asm("fma.rn.f32x2 %0, %1, %2, %0;" : "+l"(d) : "l"(a), "l"(b));
}

// ============================================================
// kHistW: (a) blocks [0,WBLKS): transpose nn_w/nn_b -> g_wbig
//         (b) remaining blocks: tile histogram + dst in-degree
// ============================================================
__global__ void kHistW(const int* __restrict__ ei,
                       const float* __restrict__ nn_w,
                       const float* __restrict__ nn_b) {
    const int b = blockIdx.x;
    const int t = threadIdx.x;
    if (b < WBLKS) {
        for (int idx = b * 256 + t; idx < 32 * ZC; idx += WBLKS * 256) {
            int i = idx / ZC;
            int c = idx - i * ZC;
            int d = c >> 5, o = c & 31;
            g_wbig[idx] = (d < 13) ? nn_w[(i * 32 + o) * 13 + d]
                                   : nn_b[i * 32 + o];
        }
    } else {
        int e = (b - WBLKS) * 256 + t;
        if (e < N_EDGES) {
            atomicAdd(&g_tcnt[ei[e] >> 5], 1);
            atomicAdd(&g_cnt[ei[N_EDGES + e]], 1.f);
        }
    }
}

// ============================================================
// kScanT: single block, exclusive scan of 3125 tile counts.
// ============================================================
__global__ void kScanT() {
    __shared__ int wsum[32];
    __shared__ int carry;
    const int t = threadIdx.x;      // 1024
    const int lane = t & 31, w = t >> 5;
    if (t == 0) carry = 0;
    __syncthreads();

#pragma unroll
    for (int c = 0; c < 4; c++) {
        const int idx = c * 1024 + t;
        int v = (idx < NT) ? g_tcnt[idx] : 0;
        int s = v;
#pragma unroll
        for (int o = 1; o < 32; o <<= 1) {
            int u = __shfl_up_sync(0xffffffffu, s, o);
            if (lane >= o) s += u;
        }
        if (lane == 31) wsum[w] = s;
        __syncthreads();
        if (w == 0) {
            int ws = wsum[lane];
#pragma unroll
            for (int o = 1; o < 32; o <<= 1) {
                int u = __shfl_up_sync(0xffffffffu, ws, o);
                if (lane >= o) ws += u;
            }
            wsum[lane] = ws;
        }
        __syncthreads();
        const int excl = carry + (w > 0 ? wsum[w - 1] : 0) + s - v;
        if (idx < NT) {
            g_toff[idx] = excl;
            g_tcur[idx] = excl;
            g_tcnt[idx] = 0;        // restore zero invariant
        }
        __syncthreads();
        if (t == 0) carry += wsum[31];
        __syncthreads();
    }
    if (t == 0) g_toff[NT] = N_EDGES;
}

// ============================================================
// kScatT: scatter edges into tile-contiguous segments.
// ============================================================
__global__ void kScatT(const int* __restrict__ ei) {
    int e = blockIdx.x * blockDim.x + threadIdx.x;
    if (e >= N_EDGES) return;
    int src = ei[e];
    int dst = ei[N_EDGES + e];
    int pos = atomicAdd(&g_tcur[src >> 5], 1);
    g_epack[pos] = ((src & 31) << 18) | e;   // eid < 2^18
    g_edst[pos] = dst;
}

// ============================================================
// kFused: 32-node tile, 14 warps, 2 CTAs/SM.
// Phase 1: warp = one 32-col block; thread = 8 nodes x 4 cols (f32x2).
//   x from duplicated smem tile (LDS.128 -> ready f32x2 pairs),
//   W streamed from L2/L1 via LDG.128 (ulonglong2 -> aligned pairs).
// Phase 2: tile's contiguous edge segment, warp-strided, pipelined.
// ============================================================
__global__ void __launch_bounds__(KF_THREADS, 2)
kFused(const float* __restrict__ x,
       const float* __restrict__ edge_attr) {
    extern __shared__ __align__(16) float sm[];
    float* zs = sm;                          // [32][452]  57856 B
    float* xd = sm + NODES_PER_BLK * ZPITCH; // [32][68]    8704 B (dup pairs)

    const int t = threadIdx.x;    // 448 = 14 warps
    const int lane = t & 31;
    const int w = t >> 5;

    // stage duplicated-x tile: xd[i][2*nl .. 2*nl+1] = (x[n][i], x[n][i])
    const int nbase = blockIdx.x * NODES_PER_BLK;
    if (t < 256) {
        const int nl = t >> 3, fq = t & 7;   // node 0..31, float4 index 0..7
        float4 v = __ldg((const float4*)(x + (size_t)(nbase + nl) * DIN + fq * 4));
        uint64_t* p = (uint64_t*)(xd + (size_t)(fq * 4) * XDP + 2 * nl);
        p[0] = pk2(v.x, v.x);
        *(uint64_t*)(xd + (size_t)(fq * 4 + 1) * XDP + 2 * nl) = pk2(v.y, v.y);
        *(uint64_t*)(xd + (size_t)(fq * 4 + 2) * XDP + 2 * nl) = pk2(v.z, v.z);
        *(uint64_t*)(xd + (size_t)(fq * 4 + 3) * XDP + 2 * nl) = pk2(v.w, v.w);
    }
    __syncthreads();

    // ---- phase 1: warp = col block cw = w (32 cols); thread = 8n x 4c ----
    const int no = lane >> 3;              // node octet (0..3)
    const int co = lane & 7;               // col quad (0..7)
    const int cbase = w * 32 + co * 4;     // global z column base

    uint64_t acc[16];                      // acc[j*2+p]: node no*8+j, cols (cbase+2p, +1)
#pragma unroll
    for (int q = 0; q < 16; q++) acc[q] = 0ull;

    const float* xrowbase = xd + no * 16;

#pragma unroll 8
    for (int i = 0; i < 32; i++) {
        const ulonglong2 wv =
            __ldg((const ulonglong2*)(g_wbig + (size_t)i * ZC + cbase));
        const ulonglong2* xrow = (const ulonglong2*)(xrowbase + (size_t)i * XDP);
        const ulonglong2 x01 = xrow[0];    // (v0,v0,v1,v1) nodes no*8+0,1
        const ulonglong2 x23 = xrow[1];
        const ulonglong2 x45 = xrow[2];
        const ulonglong2 x67 = xrow[3];

        fma2(acc[0],  x01.x, wv.x); fma2(acc[1],  x01.x, wv.y);
        fma2(acc[2],  x01.y, wv.x); fma2(acc[3],  x01.y, wv.y);
        fma2(acc[4],  x23.x, wv.x); fma2(acc[5],  x23.x, wv.y);
        fma2(acc[6],  x23.y, wv.x); fma2(acc[7],  x23.y, wv.y);
        fma2(acc[8],  x45.x, wv.x); fma2(acc[9],  x45.x, wv.y);
        fma2(acc[10], x45.y, wv.x); fma2(acc[11], x45.y, wv.y);
        fma2(acc[12], x67.x, wv.x); fma2(acc[13], x67.x, wv.y);
        fma2(acc[14], x67.y, wv.x); fma2(acc[15], x67.y, wv.y);
    }

    // store z tile (once per block; conflicts here are cheap)
#pragma unroll
    for (int j = 0; j < 8; j++) {
        ulonglong2* zo = (ulonglong2*)(zs + (size_t)(no * 8 + j) * ZPITCH + cbase);
        ulonglong2 s; s.x = acc[j * 2 + 0]; s.y = acc[j * 2 + 1];
        zo[0] = s;
    }
    __syncthreads();

    // ---- phase 2: contiguous edge segment, warp-strided, pipelined ----
    const int o0 = g_toff[blockIdx.x];
    const int o1 = g_toff[blockIdx.x + 1];

    int j = o0 + w;
    if (j < o1) {
        int pk  = __ldg(&g_epack[j]);
        int dst = __ldg(&g_edst[j]);
        float a = (lane < DE)
                ? __ldg(&edge_attr[(size_t)(pk & 0x3FFFF) * DE + lane]) : 0.f;

        while (j < o1) {
            const int jn = j + 14;
            int pkn = 0, dstn = 0; float an = 0.f;
            if (jn < o1) {
                pkn  = __ldg(&g_epack[jn]);
                dstn = __ldg(&g_edst[jn]);
                an = (lane < DE)
                   ? __ldg(&edge_attr[(size_t)(pkn & 0x3FFFF) * DE + lane]) : 0.f;
            }

            const int ls = pk >> 18;
            const float* zr = zs + (size_t)ls * ZPITCH;
            float msg = zr[13 * 32 + lane];            // bias slot
#pragma unroll
            for (int d = 0; d < DE; d++) {
                const float ad = __shfl_sync(0xffffffffu, a, d);
                msg += ad * zr[d * 32 + lane];
            }

            atomicAdd(&g_agg[(size_t)dst * DOUT + lane], msg);

            j = jn; pk = pkn; dst = dstn; a = an;
        }
    }
}

// ============================================================
// k3: mean + root GEMV + bias -> CELU -> GRU -> residual ReLU.
// Grid-stride; restores zero invariant on g_agg / g_cnt.
// ============================================================
__global__ void __launch_bounds__(256)
k3_gru(const float* __restrict__ x,
       const float* __restrict__ root,
       const float* __restrict__ bias,
       const float* __restrict__ w_ih,
       const float* __restrict__ w_hh,
       const float* __restrict__ b_ih,
       const float* __restrict__ b_hh,
       float* __restrict__ out,
       int write_h) {
    __shared__ float Rs[DIN * DOUT];
    __shared__ float WiT[32 * WP];
    __shared__ float WhT[32 * WP];
    __shared__ float Bi[96], Bh[96], Bo[32];
    __shared__ float stage_x[8][32];
    __shared__ float stage_c[8][32];

    const int t = threadIdx.x;  // 256
    for (int idx = t; idx < DIN * DOUT; idx += 256) Rs[idx] = root[idx];
    for (int idx = t; idx < 96 * 32; idx += 256) {
        int g = idx >> 5, j = idx & 31;
        WiT[j * WP + g] = w_ih[idx];
        WhT[j * WP + g] = w_hh[idx];
    }
    if (t < 96) { Bi[t] = b_ih[t]; Bh[t] = b_hh[t]; }
    if (t < 32) Bo[t] = bias[t];
    __syncthreads();

    const int w = t >> 5;
    const int lane = t & 31;

    for (int n = blockIdx.x * 8 + w; n < N_NODES; n += GRID3 * 8) {
        const float h0 = x[(size_t)n * DIN + lane];
        stage_x[w][lane] = h0;
        __syncwarp();

        const float cnt = g_cnt[n];
        const float aggv = g_agg[(size_t)n * DOUT + lane];
        g_agg[(size_t)n * DOUT + lane] = 0.f;   // restore zero invariant

        float conv = aggv / fmaxf(cnt, 1.f) + Bo[lane];
#pragma unroll
        for (int i = 0; i < 32; i++) conv += stage_x[w][i] * Rs[i * 32 + lane];

        const float c = (conv > 0.f) ? conv : expm1f(conv);
        stage_c[w][lane] = c;
        __syncwarp();

        float gr = Bi[lane], gz = Bi[32 + lane], gc = Bi[64 + lane];
        float hr = Bh[lane], hz = Bh[32 + lane], hc = Bh[64 + lane];
#pragma unroll
        for (int j = 0; j < 32; j++) {
            const float cj = stage_c[w][j];
            const float hj = stage_x[w][j];
            gr += cj * WiT[j * WP + lane];
            gz += cj * WiT[j * WP + 32 + lane];
            gc += cj * WiT[j * WP + 64 + lane];
            hr += hj * WhT[j * WP + lane];
            hz += hj * WhT[j * WP + 32 + lane];
            hc += hj * WhT[j * WP + 64 + lane];
        }

        const float r  = 1.f / (1.f + expf(-(gr + hr)));
        const float zg = 1.f / (1.f + expf(-(gz + hz)));
        const float nn = tanhf(gc + r * hc);
        const float h_new = (1.f - zg) * nn + zg * h0;

        out[(size_t)n * DOUT + lane] = fmaxf(h_new + h0, 0.f);
        if (write_h)
            out[(size_t)N_NODES * DOUT + (size_t)n * DOUT + lane] = h_new;
        __syncwarp();                   // cnt reads done across warp
        if (lane == 0) g_cnt[n] = 0.f;  // restore zero invariant
        __syncwarp();                   // protect stage arrays for next iter
    }
}

// ============================================================
extern "C" void kernel_launch(void* const* d_in, const int* in_sizes, int n_in,
                              void* d_out, int out_size) {
    const float* x         = (const float*)d_in[0];
    const float* edge_attr = (const float*)d_in[1];
    const float* nn_w      = (const float*)d_in[2];
    const float* nn_b      = (const float*)d_in[3];
    const float* root      = (const float*)d_in[4];
    const float* bias      = (const float*)d_in[5];
    const float* w_ih      = (const float*)d_in[6];
    const float* w_hh      = (const float*)d_in[7];
    const float* b_ih      = (const float*)d_in[8];
    const float* b_hh      = (const float*)d_in[9];
    const int* edge_index  = (const int*)d_in[10];
    float* out = (float*)d_out;

    const int smemF = (NODES_PER_BLK * ZPITCH + 32 * XDP) * (int)sizeof(float); // 66560
    cudaFuncSetAttribute(kFused, cudaFuncAttributeMaxDynamicSharedMemorySize, smemF);

    const int gridE = (N_EDGES + 255) / 256;      // 977

    kHistW<<<WBLKS + gridE, 256>>>(edge_index, nn_w, nn_b);   // launch 1
    kScanT<<<1, 1024>>>();                                    // launch 2
    kScatT<<<gridE, 256>>>(edge_index);                       // launch 3
    kFused<<<NT, KF_THREADS, smemF>>>(x, edge_attr);          // launch 4
    const int write_h = (out_size >= 2 * N_NODES * DOUT) ? 1 : 0;
    k3_gru<<<GRID3, 256>>>(x, root, bias, w_ih, w_hh, b_ih, b_hh, out, write_h); // 5
}